// round 7
// baseline (speedup 1.0000x reference)
#include <cuda_runtime.h>
#include <cuda_bf16.h>
#include <cstdint>

#define NN 100000
#define EE 800000

// ---------------- scratch (__device__ globals; no allocation allowed) ----------
__device__ float g_deg[NN];                       // degree -> dinv_sqrt (in place)
__device__ __align__(16) float g_agg[NN * 128];   // aggregated X (layer-1 GEMM input)
__device__ __align__(16) float g_h2[NN * 40];     // hidden @ W2 (pre-aggregation)
__device__ unsigned g_mask[1600000];              // 51.2M dropout keep-bits
// plain k-major bf16 images of W1 (hi/lo split): [k=128][n=512]
__device__ __align__(16) __nv_bfloat16 gBh[128 * 512];
__device__ __align__(16) __nv_bfloat16 gBl[128 * 512];
// bf16 images of W2 (hi/lo split): [k=512][n=40]
__device__ __align__(16) __nv_bfloat16 gW2h[512 * 40];
__device__ __align__(16) __nv_bfloat16 gW2l[512 * 40];

// ---------------- small helpers ------------------------------------------------
__device__ __forceinline__ void red4(float* p, float a, float b, float c, float d) {
    asm volatile("red.global.add.v4.f32 [%0], {%1,%2,%3,%4};"
                 :: "l"(p), "f"(a), "f"(b), "f"(c), "f"(d) : "memory");
}
__device__ __forceinline__ unsigned smem_u32(const void* p) {
    unsigned a;
    asm("{ .reg .u64 t; cvta.to.shared.u64 t, %1; cvt.u32.u64 %0, t; }" : "=r"(a) : "l"(p));
    return a;
}

// JAX threefry2x32 with key = (0, 42)
__device__ __forceinline__ void threefry42(unsigned& x0, unsigned& x1) {
    const unsigned ks0 = 0u, ks1 = 42u, ks2 = 0x1BD11BDAu ^ 42u;
    x0 += ks0; x1 += ks1;
#define TFR(r) { x0 += x1; x1 = (x1 << (r)) | (x1 >> (32 - (r))); x1 ^= x0; }
    TFR(13) TFR(15) TFR(26) TFR(6)   x0 += ks1; x1 += ks2 + 1u;
    TFR(17) TFR(29) TFR(16) TFR(24)  x0 += ks2; x1 += ks0 + 2u;
    TFR(13) TFR(15) TFR(26) TFR(6)   x0 += ks0; x1 += ks1 + 3u;
    TFR(17) TFR(29) TFR(16) TFR(24)  x0 += ks1; x1 += ks2 + 4u;
    TFR(13) TFR(15) TFR(26) TFR(6)   x0 += ks2; x1 += ks0 + 5u;
#undef TFR
}
__device__ __forceinline__ unsigned tf_bit(unsigned idx) {
    unsigned x0 = 0u, x1 = idx;
    threefry42(x0, x1);
    return (~(x0 ^ x1)) >> 31;
}

// ---------------- mma.sync / ldmatrix wrappers (base ISA) ----------------------
__device__ __forceinline__ void mma_bf16(float* c, const unsigned* a, unsigned b0, unsigned b1) {
    asm volatile(
        "mma.sync.aligned.m16n8k16.row.col.f32.bf16.bf16.f32 "
        "{%0,%1,%2,%3}, {%4,%5,%6,%7}, {%8,%9}, {%0,%1,%2,%3};"
        : "+f"(c[0]), "+f"(c[1]), "+f"(c[2]), "+f"(c[3])
        : "r"(a[0]), "r"(a[1]), "r"(a[2]), "r"(a[3]), "r"(b0), "r"(b1));
}
__device__ __forceinline__ void ldsm_x4(unsigned* r, unsigned addr) {
    asm volatile("ldmatrix.sync.aligned.m8n8.x4.shared.b16 {%0,%1,%2,%3}, [%4];"
                 : "=r"(r[0]), "=r"(r[1]), "=r"(r[2]), "=r"(r[3]) : "r"(addr));
}
__device__ __forceinline__ void ldsm_x4t(unsigned* r, unsigned addr) {
    asm volatile("ldmatrix.sync.aligned.m8n8.x4.trans.shared.b16 {%0,%1,%2,%3}, [%4];"
                 : "=r"(r[0]), "=r"(r[1]), "=r"(r[2]), "=r"(r[3]) : "r"(addr));
}
__device__ __forceinline__ void bfsplit(float v, unsigned short& h, unsigned short& l) {
    __nv_bfloat16 bh = __float2bfloat16(v);
    __nv_bfloat16 bl = __float2bfloat16(v - __bfloat162float(bh));
    h = *reinterpret_cast<unsigned short*>(&bh);
    l = *reinterpret_cast<unsigned short*>(&bl);
}

// ---------------- degree / normalization --------------------------------------
__global__ void deg_init_kernel() {
    int i = blockIdx.x * blockDim.x + threadIdx.x;
    if (i < NN) g_deg[i] = 1.0f;
}
__global__ void deg_scatter_kernel(const int* __restrict__ dst) {
    int e = blockIdx.x * blockDim.x + threadIdx.x;
    if (e < EE) atomicAdd(&g_deg[dst[e]], 1.0f);
}
__global__ void deg_fin_kernel() {
    int i = blockIdx.x * blockDim.x + threadIdx.x;
    if (i < NN) g_deg[i] = rsqrtf(g_deg[i]);
}

// ---------------- W1 & W2 -> bf16 split images ---------------------------------
__global__ void wcvt_kernel(const float* __restrict__ W1, const float* __restrict__ W2) {
    int t = blockIdx.x * blockDim.x + threadIdx.x;
    if (t < 8192) {                       // W1: [128][512] = 65536 elems
        int idx = t * 8;
        unsigned short h[8], l[8];
#pragma unroll
        for (int j = 0; j < 8; j++) bfsplit(W1[idx + j], h[j], l[j]);
        reinterpret_cast<uint4*>(gBh)[t] = make_uint4(
            (unsigned)h[0] | ((unsigned)h[1] << 16), (unsigned)h[2] | ((unsigned)h[3] << 16),
            (unsigned)h[4] | ((unsigned)h[5] << 16), (unsigned)h[6] | ((unsigned)h[7] << 16));
        reinterpret_cast<uint4*>(gBl)[t] = make_uint4(
            (unsigned)l[0] | ((unsigned)l[1] << 16), (unsigned)l[2] | ((unsigned)l[3] << 16),
            (unsigned)l[4] | ((unsigned)l[5] << 16), (unsigned)l[6] | ((unsigned)l[7] << 16));
    } else if (t < 10752) {               // W2: [512][40] = 20480 elems
        int i2 = t - 8192;
        int idx = i2 * 8;
        unsigned short h[8], l[8];
#pragma unroll
        for (int j = 0; j < 8; j++) bfsplit(W2[idx + j], h[j], l[j]);
        reinterpret_cast<uint4*>(gW2h)[i2] = make_uint4(
            (unsigned)h[0] | ((unsigned)h[1] << 16), (unsigned)h[2] | ((unsigned)h[3] << 16),
            (unsigned)h[4] | ((unsigned)h[5] << 16), (unsigned)h[6] | ((unsigned)h[7] << 16));
        reinterpret_cast<uint4*>(gW2l)[i2] = make_uint4(
            (unsigned)l[0] | ((unsigned)l[1] << 16), (unsigned)l[2] | ((unsigned)l[3] << 16),
            (unsigned)l[4] | ((unsigned)l[5] << 16), (unsigned)l[6] | ((unsigned)l[7] << 16));
    }
}

// ---------------- layer-1 aggregation ------------------------------------------
__global__ void agg1_init_kernel(const float* __restrict__ x) {
    int gid = blockIdx.x * blockDim.x + threadIdx.x;
    if (gid >= NN * 32) return;
    int node = gid >> 5;
    float di = g_deg[node];
    float s = di * di;
    float4 v = reinterpret_cast<const float4*>(x)[gid];
    reinterpret_cast<float4*>(g_agg)[gid] = make_float4(v.x * s, v.y * s, v.z * s, v.w * s);
}
// scatter + fused threefry mask (warp e -> mask words 2e, 2e+1)
__global__ void agg1_scatter_kernel(const float* __restrict__ x,
                                    const int* __restrict__ src,
                                    const int* __restrict__ dst) {
    int gid = blockIdx.x * blockDim.x + threadIdx.x;   // EE*32 threads
    int e = gid >> 5, lane = gid & 31;
    unsigned base = (unsigned)e * 64u + (unsigned)lane;
    unsigned bit0 = tf_bit(base);
    unsigned bit1 = tf_bit(base + 32u);
    unsigned w0 = __ballot_sync(0xFFFFFFFFu, bit0);
    unsigned w1 = __ballot_sync(0xFFFFFFFFu, bit1);
    if (lane == 0) {
        g_mask[2 * e]     = w0;
        g_mask[2 * e + 1] = w1;
    }
    int s = src[e], d = dst[e];
    float nrm = g_deg[s] * g_deg[d];
    float4 v = *reinterpret_cast<const float4*>(&x[s * 128 + lane * 4]);
    red4(&g_agg[d * 128 + lane * 4], v.x * nrm, v.y * nrm, v.z * nrm, v.w * nrm);
}

// ---------------- GEMM1 (mma.sync bf16 3-term): H = relu(AggX@W1+b1)*dropout ---
#define SROW 136
__global__ __launch_bounds__(256) void gemm1_mma_kernel(const float* __restrict__ bias,
                                                        float* __restrict__ H) {
    extern __shared__ char dsm[];
    __nv_bfloat16* sAh = reinterpret_cast<__nv_bfloat16*>(dsm);
    __nv_bfloat16* sAl = reinterpret_cast<__nv_bfloat16*>(dsm + 34816);
    __nv_bfloat16* sBh = reinterpret_cast<__nv_bfloat16*>(dsm + 69632);
    __nv_bfloat16* sBl = reinterpret_cast<__nv_bfloat16*>(dsm + 104448);
    __shared__ float sBias[128];

    const int t = threadIdx.x;
    const int lane = t & 31, wid = t >> 5;
    const int m0 = blockIdx.x * 128;
    const int n0 = blockIdx.y * 128;

    if (t < 128) sBias[t] = bias[n0 + t];

    {
#pragma unroll
        for (int i = 0; i < 8; i++) {
            int c = i * 256 + t;
            int k = c >> 4, c8 = c & 15;
            uint4 vh = *reinterpret_cast<const uint4*>(&gBh[k * 512 + n0 + c8 * 8]);
            uint4 vl = *reinterpret_cast<const uint4*>(&gBl[k * 512 + n0 + c8 * 8]);
            *reinterpret_cast<uint4*>(&sBh[k * SROW + c8 * 8]) = vh;
            *reinterpret_cast<uint4*>(&sBl[k * SROW + c8 * 8]) = vl;
        }
    }
    {
        int m = t >> 1, half = t & 1;
        int gr = m0 + m;
#pragma unroll
        for (int kk = 0; kk < 8; kk++) {
            int k = half * 64 + kk * 8;
            unsigned short h[8], l[8];
            if (gr < NN) {
                float4 v0 = *reinterpret_cast<const float4*>(&g_agg[gr * 128 + k]);
                float4 v1 = *reinterpret_cast<const float4*>(&g_agg[gr * 128 + k + 4]);
                float vv[8] = {v0.x, v0.y, v0.z, v0.w, v1.x, v1.y, v1.z, v1.w};
#pragma unroll
                for (int j = 0; j < 8; j++) bfsplit(vv[j], h[j], l[j]);
            } else {
#pragma unroll
                for (int j = 0; j < 8; j++) { h[j] = 0; l[j] = 0; }
            }
            uint4 ph = make_uint4((unsigned)h[0] | ((unsigned)h[1] << 16),
                                  (unsigned)h[2] | ((unsigned)h[3] << 16),
                                  (unsigned)h[4] | ((unsigned)h[5] << 16),
                                  (unsigned)h[6] | ((unsigned)h[7] << 16));
            uint4 pl = make_uint4((unsigned)l[0] | ((unsigned)l[1] << 16),
                                  (unsigned)l[2] | ((unsigned)l[3] << 16),
                                  (unsigned)l[4] | ((unsigned)l[5] << 16),
                                  (unsigned)l[6] | ((unsigned)l[7] << 16));
            *reinterpret_cast<uint4*>(&sAh[m * SROW + k]) = ph;
            *reinterpret_cast<uint4*>(&sAl[m * SROW + k]) = pl;
        }
    }
    __syncthreads();

    const int wm = wid & 3;
    const int wn = wid >> 2;
    float acc[2][8][4];
#pragma unroll
    for (int mf = 0; mf < 2; mf++)
#pragma unroll
        for (int nf = 0; nf < 8; nf++)
#pragma unroll
            for (int q = 0; q < 4; q++) acc[mf][nf][q] = 0.f;

    const unsigned aBaseH = smem_u32(sAh) +
        ((unsigned)(wm * 32 + (lane & 15)) * SROW + (unsigned)((lane >> 4) * 8)) * 2u;
    const unsigned aBaseL = aBaseH + 34816u;
    const unsigned bBaseH = smem_u32(sBh) +
        ((unsigned)(lane & 15) * SROW + (unsigned)(wn * 64 + ((lane >> 4) << 3))) * 2u;
    const unsigned bBaseL = bBaseH + 34816u;

#pragma unroll
    for (int ks = 0; ks < 8; ks++) {
        unsigned ah[2][4], al[2][4], bh[4][4], bl[4][4];
#pragma unroll
        for (int mf = 0; mf < 2; mf++) {
            ldsm_x4(ah[mf], aBaseH + (unsigned)(mf * 16 * SROW * 2) + (unsigned)(ks * 32));
            ldsm_x4(al[mf], aBaseL + (unsigned)(mf * 16 * SROW * 2) + (unsigned)(ks * 32));
        }
#pragma unroll
        for (int j = 0; j < 4; j++) {
            ldsm_x4t(bh[j], bBaseH + (unsigned)(ks * 16 * SROW * 2) + (unsigned)(j * 32));
            ldsm_x4t(bl[j], bBaseL + (unsigned)(ks * 16 * SROW * 2) + (unsigned)(j * 32));
        }
#pragma unroll
        for (int mf = 0; mf < 2; mf++) {
#pragma unroll
            for (int j = 0; j < 4; j++) {
                mma_bf16(acc[mf][2 * j],     ah[mf], bh[j][0], bh[j][1]);
                mma_bf16(acc[mf][2 * j],     ah[mf], bl[j][0], bl[j][1]);
                mma_bf16(acc[mf][2 * j],     al[mf], bh[j][0], bh[j][1]);
                mma_bf16(acc[mf][2 * j + 1], ah[mf], bh[j][2], bh[j][3]);
                mma_bf16(acc[mf][2 * j + 1], ah[mf], bl[j][2], bl[j][3]);
                mma_bf16(acc[mf][2 * j + 1], al[mf], bh[j][2], bh[j][3]);
            }
        }
    }

    const int quad = lane >> 2, qt = lane & 3;
#pragma unroll
    for (int mf = 0; mf < 2; mf++) {
#pragma unroll
        for (int p = 0; p < 2; p++) {
            int row = m0 + wm * 32 + mf * 16 + quad + p * 8;
            if (row >= NN) continue;
            unsigned mw0 = g_mask[row * 16 + ((n0 + wn * 64) >> 5)];
            unsigned mw1 = g_mask[row * 16 + ((n0 + wn * 64) >> 5) + 1];
            float* hp = H + (size_t)row * 512 + n0 + wn * 64;
#pragma unroll
            for (int nf = 0; nf < 8; nf++) {
                int cl = nf * 8 + qt * 2;
                unsigned mw = (cl < 32) ? mw0 : mw1;
                int sh = cl & 31;
                float v0 = fmaxf(acc[mf][nf][p * 2 + 0] + sBias[wn * 64 + cl + 0], 0.f) * 2.f;
                float v1 = fmaxf(acc[mf][nf][p * 2 + 1] + sBias[wn * 64 + cl + 1], 0.f) * 2.f;
                float2 o;
                o.x = ((mw >> (sh + 0)) & 1u) ? v0 : 0.f;
                o.y = ((mw >> (sh + 1)) & 1u) ? v1 : 0.f;
                *reinterpret_cast<float2*>(hp + cl) = o;
            }
        }
    }
}

// ---------------- GEMM2 (mma.sync bf16 3-term) + fused out init ----------------
// CTA: 128 rows, full N=40 (pad 48), K=512 in 8 chunks of 64. 8 warps x 16 rows.
#define AROW 72   // A tile row stride (bf16 elems)
#define WROW 48   // W2 tile row stride
__global__ __launch_bounds__(256) void gemm2_mma_kernel(const float* __restrict__ H,
                                                        const float* __restrict__ b2,
                                                        float* __restrict__ out) {
    extern __shared__ char dsm[];
    __nv_bfloat16* sAh = reinterpret_cast<__nv_bfloat16*>(dsm);              // 18432B
    __nv_bfloat16* sAl = reinterpret_cast<__nv_bfloat16*>(dsm + 18432);      // 18432B
    __nv_bfloat16* sWh = reinterpret_cast<__nv_bfloat16*>(dsm + 36864);      // 49152B
    __nv_bfloat16* sWl = reinterpret_cast<__nv_bfloat16*>(dsm + 86016);      // 49152B
    __shared__ float sB2[40];

    const int t = threadIdx.x;
    const int lane = t & 31, wid = t >> 5;
    const int m0 = blockIdx.x * 128;

    if (t < 40) sB2[t] = b2[t];

    // ---- resident W2 tiles: [512][48] hi/lo (valid cols 0-39, pad 40-47 = 0) ----
    {
        const uint4* srcH = reinterpret_cast<const uint4*>(gW2h);
        const uint4* srcL = reinterpret_cast<const uint4*>(gW2l);
#pragma unroll
        for (int i = 0; i < 10; i++) {                 // 2560 uint4 per split
            int u = i * 256 + t;
            int k = u / 5, n0c = (u % 5) * 8;
            *reinterpret_cast<uint4*>(&sWh[k * WROW + n0c]) = srcH[u];
            *reinterpret_cast<uint4*>(&sWl[k * WROW + n0c]) = srcL[u];
        }
        uint4 z = make_uint4(0u, 0u, 0u, 0u);
#pragma unroll
        for (int i = 0; i < 2; i++) {                  // zero pad cols 40-47
            int k = i * 256 + t;
            *reinterpret_cast<uint4*>(&sWh[k * WROW + 40]) = z;
            *reinterpret_cast<uint4*>(&sWl[k * WROW + 40]) = z;
        }
    }

    float acc[5][4];
#pragma unroll
    for (int nf = 0; nf < 5; nf++)
#pragma unroll
        for (int q = 0; q < 4; q++) acc[nf][q] = 0.f;

    const unsigned aBaseH = smem_u32(sAh) +
        ((unsigned)(wid * 16 + (lane & 15)) * AROW + (unsigned)((lane >> 4) * 8)) * 2u;
    const unsigned aBaseL = aBaseH + 18432u;
    const unsigned wBaseH = smem_u32(sWh) + ((unsigned)(lane & 15) * WROW +
                                             (unsigned)((lane >> 4) * 8)) * 2u;
    const unsigned wBaseL = wBaseH + 49152u;

    for (int kc = 0; kc < 8; kc++) {
        __syncthreads();   // W2 fill (first iter) / previous mma done
        // ---- A tile: H[m0..m0+127][kc*64..+63] fp32 -> bf16 hi/lo split ----
#pragma unroll
        for (int i = 0; i < 8; i++) {
            int idx = i * 256 + t;                     // 2048 float4
            int m = idx >> 4, c4 = idx & 15;
            int gr = m0 + m;
            unsigned short h[4], l[4];
            if (gr < NN) {
                float4 v = *reinterpret_cast<const float4*>(&H[(size_t)gr * 512 + kc * 64 + c4 * 4]);
                bfsplit(v.x, h[0], l[0]); bfsplit(v.y, h[1], l[1]);
                bfsplit(v.z, h[2], l[2]); bfsplit(v.w, h[3], l[3]);
            } else {
#pragma unroll
                for (int j = 0; j < 4; j++) { h[j] = 0; l[j] = 0; }
            }
            uint2 ph = make_uint2((unsigned)h[0] | ((unsigned)h[1] << 16),
                                  (unsigned)h[2] | ((unsigned)h[3] << 16));
            uint2 pl = make_uint2((unsigned)l[0] | ((unsigned)l[1] << 16),
                                  (unsigned)l[2] | ((unsigned)l[3] << 16));
            *reinterpret_cast<uint2*>(&sAh[m * AROW + c4 * 4]) = ph;
            *reinterpret_cast<uint2*>(&sAl[m * AROW + c4 * 4]) = pl;
        }
        __syncthreads();
        // ---- 4 k-steps of m16n8k16 ----
#pragma unroll
        for (int ks = 0; ks < 4; ks++) {
            unsigned ah[4], al[4], bh[12], bl[12];
            ldsm_x4(ah, aBaseH + (unsigned)(ks * 32));
            ldsm_x4(al, aBaseL + (unsigned)(ks * 32));
            unsigned ko = (unsigned)((kc * 64 + ks * 16) * WROW * 2);
            ldsm_x4t(&bh[0], wBaseH + ko);
            ldsm_x4t(&bh[4], wBaseH + ko + 32u);
            ldsm_x4t(&bh[8], wBaseH + ko + 64u);
            ldsm_x4t(&bl[0], wBaseL + ko);
            ldsm_x4t(&bl[4], wBaseL + ko + 32u);
            ldsm_x4t(&bl[8], wBaseL + ko + 64u);
#pragma unroll
            for (int nf = 0; nf < 5; nf++) {
                mma_bf16(acc[nf], ah, bh[nf * 2], bh[nf * 2 + 1]);
                mma_bf16(acc[nf], ah, bl[nf * 2], bl[nf * 2 + 1]);
                mma_bf16(acc[nf], al, bh[nf * 2], bh[nf * 2 + 1]);
            }
        }
    }

    // ---- epilogue: g_h2 store + fused out = b2 + s*h2 ----
    const int quad = lane >> 2, qt = lane & 3;
#pragma unroll
    for (int p = 0; p < 2; p++) {
        int row = m0 + wid * 16 + quad + p * 8;
        if (row >= NN) continue;
        float di = g_deg[row];
        float s = di * di;
#pragma unroll
        for (int nf = 0; nf < 5; nf++) {
            int col = nf * 8 + qt * 2;
            float v0 = acc[nf][p * 2 + 0];
            float v1 = acc[nf][p * 2 + 1];
            *reinterpret_cast<float2*>(&g_h2[row * 40 + col]) = make_float2(v0, v1);
            *reinterpret_cast<float2*>(&out[row * 40 + col]) =
                make_float2(sB2[col] + v0 * s, sB2[col + 1] + v1 * s);
        }
    }
}

// ---------------- layer-2 scatter: out += norm * g_h2[src] ---------------------
__global__ void agg2_scatter_kernel(const int* __restrict__ src,
                                    const int* __restrict__ dst,
                                    float* __restrict__ out) {
    int gid = blockIdx.x * blockDim.x + threadIdx.x;
    int e = gid / 10;
    int c = gid - e * 10;
    if (e >= EE) return;
    int s = src[e], d = dst[e];
    float nrm = g_deg[s] * g_deg[d];
    float4 v = *reinterpret_cast<const float4*>(&g_h2[s * 40 + c * 4]);
    red4(&out[d * 40 + c * 4], v.x * nrm, v.y * nrm, v.z * nrm, v.w * nrm);
}

// ---------------- launch --------------------------------------------------------
extern "C" void kernel_launch(void* const* d_in, const int* in_sizes, int n_in,
                              void* d_out, int out_size) {
    const float* x  = (const float*)d_in[0];
    const int*   ei = (const int*)d_in[1];
    const float* W1 = (const float*)d_in[2];
    const float* b1 = (const float*)d_in[3];
    const float* W2 = (const float*)d_in[4];
    const float* b2 = (const float*)d_in[5];
    (void)in_sizes; (void)n_in; (void)out_size;

    float* out = (float*)d_out;           // [NN, 40]
    float* hidden = out + NN * 40;        // [NN, 512]
    const int* src = ei;
    const int* dst = ei + EE;

    const int GEMM1_SMEM = 139264;
    cudaFuncSetAttribute(gemm1_mma_kernel,
                         cudaFuncAttributeMaxDynamicSharedMemorySize, GEMM1_SMEM);
    const int GEMM2_SMEM = 135168;
    cudaFuncSetAttribute(gemm2_mma_kernel,
                         cudaFuncAttributeMaxDynamicSharedMemorySize, GEMM2_SMEM);

    deg_init_kernel<<<(NN + 255) / 256, 256>>>();
    deg_scatter_kernel<<<(EE + 255) / 256, 256>>>(dst);
    deg_fin_kernel<<<(NN + 255) / 256, 256>>>();

    wcvt_kernel<<<43, 256>>>(W1, W2);

    agg1_init_kernel<<<(NN * 32) / 256, 256>>>(x);
    agg1_scatter_kernel<<<(EE * 32) / 256, 256>>>(x, src, dst);  // + fused mask

    gemm1_mma_kernel<<<dim3((NN + 127) / 128, 4), 256, GEMM1_SMEM>>>(b1, hidden);
    gemm2_mma_kernel<<<(NN + 127) / 128, 256, GEMM2_SMEM>>>(hidden, b2, out);

    agg2_scatter_kernel<<<(EE * 10 + 255) / 256, 256>>>(src, dst, out);
}

// round 8
// speedup vs baseline: 1.2850x; 1.2850x over previous
#include <cuda_runtime.h>
#include <cuda_bf16.h>
#include <cstdint>

#define NN 100000
#define EE 800000

// ---------------- scratch (__device__ globals; no allocation allowed) ----------
__device__ float g_deg[NN];                       // dinv_sqrt
__device__ int   g_cnt[NN];                       // in-degree counts
__device__ int   g_off[NN + 1];                   // CSR offsets (by dst)
__device__ int   g_fill[NN];                      // fill cursors
__device__ int   g_csr[EE];                       // src ids grouped by dst
__device__ int   g_bsum[512];                     // scan block sums
__device__ __align__(16) float g_agg[NN * 128];   // aggregated X (layer-1 GEMM input)
__device__ __align__(16) float g_h2[NN * 40];     // hidden @ W2 (pre-aggregation)
__device__ unsigned g_mask[1600000];              // 51.2M dropout keep-bits
// plain k-major bf16 images of W1 (hi/lo split): [k=128][n=512]
__device__ __align__(16) __nv_bfloat16 gBh[128 * 512];
__device__ __align__(16) __nv_bfloat16 gBl[128 * 512];

// ---------------- small helpers ------------------------------------------------
__device__ __forceinline__ unsigned long long pack2(float x, float y) {
    unsigned long long r;
    asm("mov.b64 %0, {%1, %2};" : "=l"(r) : "f"(x), "f"(y));
    return r;
}
__device__ __forceinline__ unsigned long long fma2(unsigned long long a,
                                                   unsigned long long b,
                                                   unsigned long long c) {
    unsigned long long d;
    asm("fma.rn.f32x2 %0, %1, %2, %3;" : "=l"(d) : "l"(a), "l"(b), "l"(c));
    return d;
}
__device__ __forceinline__ void red4(float* p, float a, float b, float c, float d) {
    asm volatile("red.global.add.v4.f32 [%0], {%1,%2,%3,%4};"
                 :: "l"(p), "f"(a), "f"(b), "f"(c), "f"(d) : "memory");
}
__device__ __forceinline__ unsigned smem_u32(const void* p) {
    unsigned a;
    asm("{ .reg .u64 t; cvta.to.shared.u64 t, %1; cvt.u32.u64 %0, t; }" : "=r"(a) : "l"(p));
    return a;
}

// JAX threefry2x32 with key = (0, 42)
__device__ __forceinline__ void threefry42(unsigned& x0, unsigned& x1) {
    const unsigned ks0 = 0u, ks1 = 42u, ks2 = 0x1BD11BDAu ^ 42u;
    x0 += ks0; x1 += ks1;
#define TFR(r) { x0 += x1; x1 = (x1 << (r)) | (x1 >> (32 - (r))); x1 ^= x0; }
    TFR(13) TFR(15) TFR(26) TFR(6)   x0 += ks1; x1 += ks2 + 1u;
    TFR(17) TFR(29) TFR(16) TFR(24)  x0 += ks2; x1 += ks0 + 2u;
    TFR(13) TFR(15) TFR(26) TFR(6)   x0 += ks0; x1 += ks1 + 3u;
    TFR(17) TFR(29) TFR(16) TFR(24)  x0 += ks1; x1 += ks2 + 4u;
    TFR(13) TFR(15) TFR(26) TFR(6)   x0 += ks2; x1 += ks0 + 5u;
#undef TFR
}
__device__ __forceinline__ unsigned tf_bit(unsigned idx) {
    unsigned x0 = 0u, x1 = idx;
    threefry42(x0, x1);
    return (~(x0 ^ x1)) >> 31;
}

// ---------------- mma.sync / ldmatrix wrappers ----------------------------------
__device__ __forceinline__ void mma_bf16(float* c, const unsigned* a, unsigned b0, unsigned b1) {
    asm volatile(
        "mma.sync.aligned.m16n8k16.row.col.f32.bf16.bf16.f32 "
        "{%0,%1,%2,%3}, {%4,%5,%6,%7}, {%8,%9}, {%0,%1,%2,%3};"
        : "+f"(c[0]), "+f"(c[1]), "+f"(c[2]), "+f"(c[3])
        : "r"(a[0]), "r"(a[1]), "r"(a[2]), "r"(a[3]), "r"(b0), "r"(b1));
}
__device__ __forceinline__ void ldsm_x4(unsigned* r, unsigned addr) {
    asm volatile("ldmatrix.sync.aligned.m8n8.x4.shared.b16 {%0,%1,%2,%3}, [%4];"
                 : "=r"(r[0]), "=r"(r[1]), "=r"(r[2]), "=r"(r[3]) : "r"(addr));
}
__device__ __forceinline__ void ldsm_x4t(unsigned* r, unsigned addr) {
    asm volatile("ldmatrix.sync.aligned.m8n8.x4.trans.shared.b16 {%0,%1,%2,%3}, [%4];"
                 : "=r"(r[0]), "=r"(r[1]), "=r"(r[2]), "=r"(r[3]) : "r"(addr));
}
__device__ __forceinline__ void bfsplit(float v, unsigned short& h, unsigned short& l) {
    __nv_bfloat16 bh = __float2bfloat16(v);
    __nv_bfloat16 bl = __float2bfloat16(v - __bfloat162float(bh));
    h = *reinterpret_cast<unsigned short*>(&bh);
    l = *reinterpret_cast<unsigned short*>(&bl);
}

// ---------------- degree / CSR build --------------------------------------------
__global__ void deg_init_kernel() {
    int i = blockIdx.x * blockDim.x + threadIdx.x;
    if (i < NN) g_cnt[i] = 0;
}
__global__ void deg_count_kernel(const int* __restrict__ dst) {
    int e = blockIdx.x * blockDim.x + threadIdx.x;
    if (e < EE) atomicAdd(&g_cnt[dst[e]], 1);
}
__global__ void deg_fin_kernel() {
    int i = blockIdx.x * blockDim.x + threadIdx.x;
    if (i < NN) g_deg[i] = rsqrtf((float)g_cnt[i] + 1.0f);
}
// scan1: per-block exclusive scan of counts; block total -> g_bsum
__global__ void scan1_kernel() {
    __shared__ int sc[256];
    int t = threadIdx.x;
    int i = blockIdx.x * 256 + t;
    int val = (i < NN) ? g_cnt[i] : 0;
    sc[t] = val;
    __syncthreads();
#pragma unroll
    for (int d = 1; d < 256; d <<= 1) {
        int v = (t >= d) ? sc[t - d] : 0;
        __syncthreads();
        sc[t] += v;
        __syncthreads();
    }
    if (i < NN) g_off[i] = sc[t] - val;       // exclusive within block
    if (t == 255) g_bsum[blockIdx.x] = sc[255];
}
// scan2: exclusive scan of 391 block sums (single block)
__global__ void scan2_kernel() {
    __shared__ int sc[512];
    int t = threadIdx.x;
    int val = (t < 391) ? g_bsum[t] : 0;
    sc[t] = val;
    __syncthreads();
#pragma unroll
    for (int d = 1; d < 512; d <<= 1) {
        int v = (t >= d) ? sc[t - d] : 0;
        __syncthreads();
        sc[t] += v;
        __syncthreads();
    }
    if (t < 391) g_bsum[t] = sc[t] - val;     // exclusive
}
// scan3: add block offsets; zero fill cursors; set g_off[NN]
__global__ void scan3_kernel() {
    int i = blockIdx.x * blockDim.x + threadIdx.x;
    if (i < NN) {
        g_off[i] += g_bsum[i >> 8];
        g_fill[i] = 0;
    }
    if (i == 0) g_off[NN] = EE;
}
__global__ void fill_kernel(const int* __restrict__ src, const int* __restrict__ dst) {
    int e = blockIdx.x * blockDim.x + threadIdx.x;
    if (e >= EE) return;
    int d = dst[e];
    int pos = g_off[d] + atomicAdd(&g_fill[d], 1);
    g_csr[pos] = src[e];
}

// ---------------- W1 -> plain k-major bf16 split images -------------------------
__global__ void w1cvt_kernel(const float* __restrict__ W1) {
    int t = blockIdx.x * blockDim.x + threadIdx.x;
    if (t >= 8192) return;
    int idx = t * 8;
    unsigned short h[8], l[8];
#pragma unroll
    for (int j = 0; j < 8; j++) bfsplit(W1[idx + j], h[j], l[j]);
    reinterpret_cast<uint4*>(gBh)[t] = make_uint4(
        (unsigned)h[0] | ((unsigned)h[1] << 16), (unsigned)h[2] | ((unsigned)h[3] << 16),
        (unsigned)h[4] | ((unsigned)h[5] << 16), (unsigned)h[6] | ((unsigned)h[7] << 16));
    reinterpret_cast<uint4*>(gBl)[t] = make_uint4(
        (unsigned)l[0] | ((unsigned)l[1] << 16), (unsigned)l[2] | ((unsigned)l[3] << 16),
        (unsigned)l[4] | ((unsigned)l[5] << 16), (unsigned)l[6] | ((unsigned)l[7] << 16));
}

// ---------------- layer-1 aggregation: CSR gather + fused threefry mask ---------
// One warp per node. acc = dinv^2 * x[n] + sum_j dinv[s]*dinv[n] * x[s].
// Mask: warp n computes 16 words of row n (lane b -> bit b of each word).
__global__ __launch_bounds__(256) void agg1_gather_kernel(const float* __restrict__ x) {
    int wg = blockIdx.x * 8 + (threadIdx.x >> 5);   // warp id = node (grid exact)
    int lane = threadIdx.x & 31;
    int n = wg;

    const float4* x4 = reinterpret_cast<const float4*>(x);
    float dn = g_deg[n];
    float4 xv = x4[n * 32 + lane];
    float s0 = dn * dn;
    float4 acc = make_float4(xv.x * s0, xv.y * s0, xv.z * s0, xv.w * s0);

    int beg = g_off[n], end = g_off[n + 1];
    for (int j = beg; j < end; j++) {
        int s = g_csr[j];                 // broadcast load
        float nrm = g_deg[s] * dn;        // broadcast load
        float4 v = x4[s * 32 + lane];
        acc.x += nrm * v.x; acc.y += nrm * v.y;
        acc.z += nrm * v.z; acc.w += nrm * v.w;
    }
    reinterpret_cast<float4*>(g_agg)[n * 32 + lane] = acc;

    // dropout mask for hidden row n (512 bits = 16 words)
    unsigned base = (unsigned)n * 512u + (unsigned)lane;
#pragma unroll
    for (int w = 0; w < 16; w++) {
        unsigned bit = tf_bit(base + (unsigned)w * 32u);
        unsigned word = __ballot_sync(0xFFFFFFFFu, bit);
        if (lane == 0) g_mask[n * 16 + w] = word;
    }
}

// ---------------- GEMM1 (mma.sync bf16 3-term): H = relu(AggX@W1+b1)*dropout ---
#define SROW 136
__global__ __launch_bounds__(256) void gemm1_mma_kernel(const float* __restrict__ bias,
                                                        float* __restrict__ H) {
    extern __shared__ char dsm[];
    __nv_bfloat16* sAh = reinterpret_cast<__nv_bfloat16*>(dsm);
    __nv_bfloat16* sAl = reinterpret_cast<__nv_bfloat16*>(dsm + 34816);
    __nv_bfloat16* sBh = reinterpret_cast<__nv_bfloat16*>(dsm + 69632);
    __nv_bfloat16* sBl = reinterpret_cast<__nv_bfloat16*>(dsm + 104448);
    __shared__ float sBias[128];

    const int t = threadIdx.x;
    const int lane = t & 31, wid = t >> 5;
    const int m0 = blockIdx.x * 128;
    const int n0 = blockIdx.y * 128;

    if (t < 128) sBias[t] = bias[n0 + t];

    {
#pragma unroll
        for (int i = 0; i < 8; i++) {
            int c = i * 256 + t;
            int k = c >> 4, c8 = c & 15;
            uint4 vh = *reinterpret_cast<const uint4*>(&gBh[k * 512 + n0 + c8 * 8]);
            uint4 vl = *reinterpret_cast<const uint4*>(&gBl[k * 512 + n0 + c8 * 8]);
            *reinterpret_cast<uint4*>(&sBh[k * SROW + c8 * 8]) = vh;
            *reinterpret_cast<uint4*>(&sBl[k * SROW + c8 * 8]) = vl;
        }
    }
    {
        int m = t >> 1, half = t & 1;
        int gr = m0 + m;
#pragma unroll
        for (int kk = 0; kk < 8; kk++) {
            int k = half * 64 + kk * 8;
            unsigned short h[8], l[8];
            if (gr < NN) {
                float4 v0 = *reinterpret_cast<const float4*>(&g_agg[gr * 128 + k]);
                float4 v1 = *reinterpret_cast<const float4*>(&g_agg[gr * 128 + k + 4]);
                float vv[8] = {v0.x, v0.y, v0.z, v0.w, v1.x, v1.y, v1.z, v1.w};
#pragma unroll
                for (int j = 0; j < 8; j++) bfsplit(vv[j], h[j], l[j]);
            } else {
#pragma unroll
                for (int j = 0; j < 8; j++) { h[j] = 0; l[j] = 0; }
            }
            uint4 ph = make_uint4((unsigned)h[0] | ((unsigned)h[1] << 16),
                                  (unsigned)h[2] | ((unsigned)h[3] << 16),
                                  (unsigned)h[4] | ((unsigned)h[5] << 16),
                                  (unsigned)h[6] | ((unsigned)h[7] << 16));
            uint4 pl = make_uint4((unsigned)l[0] | ((unsigned)l[1] << 16),
                                  (unsigned)l[2] | ((unsigned)l[3] << 16),
                                  (unsigned)l[4] | ((unsigned)l[5] << 16),
                                  (unsigned)l[6] | ((unsigned)l[7] << 16));
            *reinterpret_cast<uint4*>(&sAh[m * SROW + k]) = ph;
            *reinterpret_cast<uint4*>(&sAl[m * SROW + k]) = pl;
        }
    }
    __syncthreads();

    const int wm = wid & 3;
    const int wn = wid >> 2;
    float acc[2][8][4];
#pragma unroll
    for (int mf = 0; mf < 2; mf++)
#pragma unroll
        for (int nf = 0; nf < 8; nf++)
#pragma unroll
            for (int q = 0; q < 4; q++) acc[mf][nf][q] = 0.f;

    const unsigned aBaseH = smem_u32(sAh) +
        ((unsigned)(wm * 32 + (lane & 15)) * SROW + (unsigned)((lane >> 4) * 8)) * 2u;
    const unsigned aBaseL = aBaseH + 34816u;
    const unsigned bBaseH = smem_u32(sBh) +
        ((unsigned)(lane & 15) * SROW + (unsigned)(wn * 64 + ((lane >> 4) << 3))) * 2u;
    const unsigned bBaseL = bBaseH + 34816u;

#pragma unroll
    for (int ks = 0; ks < 8; ks++) {
        unsigned ah[2][4], al[2][4], bh[4][4], bl[4][4];
#pragma unroll
        for (int mf = 0; mf < 2; mf++) {
            ldsm_x4(ah[mf], aBaseH + (unsigned)(mf * 16 * SROW * 2) + (unsigned)(ks * 32));
            ldsm_x4(al[mf], aBaseL + (unsigned)(mf * 16 * SROW * 2) + (unsigned)(ks * 32));
        }
#pragma unroll
        for (int j = 0; j < 4; j++) {
            ldsm_x4t(bh[j], bBaseH + (unsigned)(ks * 16 * SROW * 2) + (unsigned)(j * 32));
            ldsm_x4t(bl[j], bBaseL + (unsigned)(ks * 16 * SROW * 2) + (unsigned)(j * 32));
        }
#pragma unroll
        for (int mf = 0; mf < 2; mf++) {
#pragma unroll
            for (int j = 0; j < 4; j++) {
                mma_bf16(acc[mf][2 * j],     ah[mf], bh[j][0], bh[j][1]);
                mma_bf16(acc[mf][2 * j],     ah[mf], bl[j][0], bl[j][1]);
                mma_bf16(acc[mf][2 * j],     al[mf], bh[j][0], bh[j][1]);
                mma_bf16(acc[mf][2 * j + 1], ah[mf], bh[j][2], bh[j][3]);
                mma_bf16(acc[mf][2 * j + 1], ah[mf], bl[j][2], bl[j][3]);
                mma_bf16(acc[mf][2 * j + 1], al[mf], bh[j][2], bh[j][3]);
            }
        }
    }

    const int quad = lane >> 2, qt = lane & 3;
#pragma unroll
    for (int mf = 0; mf < 2; mf++) {
#pragma unroll
        for (int p = 0; p < 2; p++) {
            int row = m0 + wm * 32 + mf * 16 + quad + p * 8;
            if (row >= NN) continue;
            unsigned mw0 = g_mask[row * 16 + ((n0 + wn * 64) >> 5)];
            unsigned mw1 = g_mask[row * 16 + ((n0 + wn * 64) >> 5) + 1];
            float* hp = H + (size_t)row * 512 + n0 + wn * 64;
#pragma unroll
            for (int nf = 0; nf < 8; nf++) {
                int cl = nf * 8 + qt * 2;
                unsigned mw = (cl < 32) ? mw0 : mw1;
                int sh = cl & 31;
                float v0 = fmaxf(acc[mf][nf][p * 2 + 0] + sBias[wn * 64 + cl + 0], 0.f) * 2.f;
                float v1 = fmaxf(acc[mf][nf][p * 2 + 1] + sBias[wn * 64 + cl + 1], 0.f) * 2.f;
                float2 o;
                o.x = ((mw >> (sh + 0)) & 1u) ? v0 : 0.f;
                o.y = ((mw >> (sh + 1)) & 1u) ? v1 : 0.f;
                *reinterpret_cast<float2*>(hp + cl) = o;
            }
        }
    }
}

// ---------------- GEMM2 (FFMA2): g_h2 = H @ W2, fused out init -----------------
__global__ __launch_bounds__(256) void gemm2_kernel(const float* __restrict__ H,
                                                    const float* __restrict__ W2,
                                                    const float* __restrict__ b2,
                                                    float* __restrict__ out) {
    __shared__ __align__(16) float As[32][260];
    __shared__ __align__(16) float Ws[32][40];
    const int t = threadIdx.x;
    const int rg = t & 63;
    const int cg = t >> 6;
    const int m0 = blockIdx.x * 256;

    unsigned long long acc[4][5];
#pragma unroll
    for (int i = 0; i < 4; i++)
#pragma unroll
        for (int j = 0; j < 5; j++) acc[i][j] = 0ull;

    const int akq = t & 7;
    const int am = t >> 3;

    for (int kc = 0; kc < 16; kc++) {
#pragma unroll
        for (int p = 0; p < 8; p++) {
            int m = p * 32 + am;
            int gr = m0 + m;
            float4 v = make_float4(0.f, 0.f, 0.f, 0.f);
            if (gr < NN)
                v = *reinterpret_cast<const float4*>(&H[gr * 512 + kc * 32 + akq * 4]);
            As[akq * 4 + 0][m] = v.x;
            As[akq * 4 + 1][m] = v.y;
            As[akq * 4 + 2][m] = v.z;
            As[akq * 4 + 3][m] = v.w;
        }
#pragma unroll
        for (int p = 0; p < 2; p++) {
            int idx = p * 256 + t;
            if (idx < 320) {
                int k = idx / 10, c = idx % 10;
                *reinterpret_cast<float4*>(&Ws[k][c * 4]) =
                    *reinterpret_cast<const float4*>(&W2[(kc * 32 + k) * 40 + c * 4]);
            }
        }
        __syncthreads();
#pragma unroll
        for (int k = 0; k < 32; k++) {
            float4 a = *reinterpret_cast<const float4*>(&As[k][rg * 4]);
            const float* wr = &Ws[k][cg * 10];
            unsigned long long w0 = *reinterpret_cast<const unsigned long long*>(wr + 0);
            unsigned long long w1 = *reinterpret_cast<const unsigned long long*>(wr + 2);
            unsigned long long w2 = *reinterpret_cast<const unsigned long long*>(wr + 4);
            unsigned long long w3 = *reinterpret_cast<const unsigned long long*>(wr + 6);
            unsigned long long w4 = *reinterpret_cast<const unsigned long long*>(wr + 8);
            float av[4] = {a.x, a.y, a.z, a.w};
#pragma unroll
            for (int i = 0; i < 4; i++) {
                unsigned long long ai = pack2(av[i], av[i]);
                acc[i][0] = fma2(ai, w0, acc[i][0]);
                acc[i][1] = fma2(ai, w1, acc[i][1]);
                acc[i][2] = fma2(ai, w2, acc[i][2]);
                acc[i][3] = fma2(ai, w3, acc[i][3]);
                acc[i][4] = fma2(ai, w4, acc[i][4]);
            }
        }
        __syncthreads();
    }
#pragma unroll
    for (int i = 0; i < 4; i++) {
        int row = m0 + rg * 4 + i;
        if (row >= NN) continue;
        float di = g_deg[row];
        float s = di * di;
#pragma unroll
        for (int j = 0; j < 5; j++) {
            int c = cg * 10 + j * 2;
            float2 v = *reinterpret_cast<float2*>(&acc[i][j]);
            *reinterpret_cast<unsigned long long*>(&g_h2[row * 40 + c]) = acc[i][j];
            float2 bb = *reinterpret_cast<const float2*>(&b2[c]);
            *reinterpret_cast<float2*>(&out[row * 40 + c]) =
                make_float2(bb.x + v.x * s, bb.y + v.y * s);
        }
    }
}

// ---------------- layer-2 scatter: out += norm * g_h2[src] ---------------------
__global__ void agg2_scatter_kernel(const int* __restrict__ src,
                                    const int* __restrict__ dst,
                                    float* __restrict__ out) {
    int gid = blockIdx.x * blockDim.x + threadIdx.x;
    int e = gid / 10;
    int c = gid - e * 10;
    if (e >= EE) return;
    int s = src[e], d = dst[e];
    float nrm = g_deg[s] * g_deg[d];
    float4 v = *reinterpret_cast<const float4*>(&g_h2[s * 40 + c * 4]);
    red4(&out[d * 40 + c * 4], v.x * nrm, v.y * nrm, v.z * nrm, v.w * nrm);
}

// ---------------- launch --------------------------------------------------------
extern "C" void kernel_launch(void* const* d_in, const int* in_sizes, int n_in,
                              void* d_out, int out_size) {
    const float* x  = (const float*)d_in[0];
    const int*   ei = (const int*)d_in[1];
    const float* W1 = (const float*)d_in[2];
    const float* b1 = (const float*)d_in[3];
    const float* W2 = (const float*)d_in[4];
    const float* b2 = (const float*)d_in[5];
    (void)in_sizes; (void)n_in; (void)out_size;

    float* out = (float*)d_out;           // [NN, 40]
    float* hidden = out + NN * 40;        // [NN, 512]
    const int* src = ei;
    const int* dst = ei + EE;

    const int GEMM1_SMEM = 139264;
    cudaFuncSetAttribute(gemm1_mma_kernel,
                         cudaFuncAttributeMaxDynamicSharedMemorySize, GEMM1_SMEM);

    // degree + CSR build
    deg_init_kernel<<<(NN + 255) / 256, 256>>>();
    deg_count_kernel<<<(EE + 255) / 256, 256>>>(dst);
    deg_fin_kernel<<<(NN + 255) / 256, 256>>>();
    scan1_kernel<<<391, 256>>>();
    scan2_kernel<<<1, 512>>>();
    scan3_kernel<<<(NN + 255) / 256, 256>>>();
    fill_kernel<<<(EE + 255) / 256, 256>>>(src, dst);

    w1cvt_kernel<<<32, 256>>>(W1);

    // layer-1 aggregation (gather) + fused dropout mask
    agg1_gather_kernel<<<12500, 256>>>(x);

    gemm1_mma_kernel<<<dim3((NN + 127) / 128, 4), 256, GEMM1_SMEM>>>(b1, hidden);
    gemm2_kernel<<<(NN + 255) / 256, 256>>>(hidden, W2, b2, out);

    agg2_scatter_kernel<<<(EE * 10 + 255) / 256, 256>>>(src, dst, out);
}

// round 9
// speedup vs baseline: 1.6758x; 1.3042x over previous
#include <cuda_runtime.h>
#include <cuda_fp16.h>
#include <cstdint>

#define NN 100000
#define EE 800000

// ---------------- scratch (__device__ globals; no allocation allowed) ----------
__device__ float g_deg[NN];                       // dinv_sqrt
__device__ int   g_cnt[NN];                       // in-degree counts
__device__ int   g_off[NN + 1];                   // CSR offsets (by dst)
__device__ int   g_fill[NN];                      // fill cursors
__device__ int   g_csr[EE];                       // src ids grouped by dst
__device__ int   g_bsum[512];                     // scan block sums
__device__ __align__(16) __half gA16[NN * 128];   // aggregated X, fp16 (GEMM1 A)
__device__ __align__(16) float g_h2[NN * 40];     // hidden @ W2 (pre-aggregation)
__device__ unsigned g_mask[1600000];              // 51.2M dropout keep-bits
// k-major fp16 images of W1 (hi/lo split): [k=128][n=512]
__device__ __align__(16) __half gW1h[128 * 512];
__device__ __align__(16) __half gW1l[128 * 512];

// ---------------- small helpers ------------------------------------------------
__device__ __forceinline__ unsigned long long pack2(float x, float y) {
    unsigned long long r;
    asm("mov.b64 %0, {%1, %2};" : "=l"(r) : "f"(x), "f"(y));
    return r;
}
__device__ __forceinline__ unsigned long long fma2(unsigned long long a,
                                                   unsigned long long b,
                                                   unsigned long long c) {
    unsigned long long d;
    asm("fma.rn.f32x2 %0, %1, %2, %3;" : "=l"(d) : "l"(a), "l"(b), "l"(c));
    return d;
}
__device__ __forceinline__ unsigned smem_u32(const void* p) {
    unsigned a;
    asm("{ .reg .u64 t; cvta.to.shared.u64 t, %1; cvt.u32.u64 %0, t; }" : "=r"(a) : "l"(p));
    return a;
}

// JAX threefry2x32 with key = (0, 42)
__device__ __forceinline__ void threefry42(unsigned& x0, unsigned& x1) {
    const unsigned ks0 = 0u, ks1 = 42u, ks2 = 0x1BD11BDAu ^ 42u;
    x0 += ks0; x1 += ks1;
#define TFR(r) { x0 += x1; x1 = (x1 << (r)) | (x1 >> (32 - (r))); x1 ^= x0; }
    TFR(13) TFR(15) TFR(26) TFR(6)   x0 += ks1; x1 += ks2 + 1u;
    TFR(17) TFR(29) TFR(16) TFR(24)  x0 += ks2; x1 += ks0 + 2u;
    TFR(13) TFR(15) TFR(26) TFR(6)   x0 += ks0; x1 += ks1 + 3u;
    TFR(17) TFR(29) TFR(16) TFR(24)  x0 += ks1; x1 += ks2 + 4u;
    TFR(13) TFR(15) TFR(26) TFR(6)   x0 += ks2; x1 += ks0 + 5u;
#undef TFR
}
__device__ __forceinline__ unsigned tf_bit(unsigned idx) {
    unsigned x0 = 0u, x1 = idx;
    threefry42(x0, x1);
    return (~(x0 ^ x1)) >> 31;
}

// ---------------- mma.sync / ldmatrix wrappers ----------------------------------
__device__ __forceinline__ void mma_f16(float* c, const unsigned* a, unsigned b0, unsigned b1) {
    asm volatile(
        "mma.sync.aligned.m16n8k16.row.col.f32.f16.f16.f32 "
        "{%0,%1,%2,%3}, {%4,%5,%6,%7}, {%8,%9}, {%0,%1,%2,%3};"
        : "+f"(c[0]), "+f"(c[1]), "+f"(c[2]), "+f"(c[3])
        : "r"(a[0]), "r"(a[1]), "r"(a[2]), "r"(a[3]), "r"(b0), "r"(b1));
}
__device__ __forceinline__ void ldsm_x4(unsigned* r, unsigned addr) {
    asm volatile("ldmatrix.sync.aligned.m8n8.x4.shared.b16 {%0,%1,%2,%3}, [%4];"
                 : "=r"(r[0]), "=r"(r[1]), "=r"(r[2]), "=r"(r[3]) : "r"(addr));
}
__device__ __forceinline__ void ldsm_x4t(unsigned* r, unsigned addr) {
    asm volatile("ldmatrix.sync.aligned.m8n8.x4.trans.shared.b16 {%0,%1,%2,%3}, [%4];"
                 : "=r"(r[0]), "=r"(r[1]), "=r"(r[2]), "=r"(r[3]) : "r"(addr));
}
__device__ __forceinline__ void hsplit(float v, unsigned short& h, unsigned short& l) {
    __half hh = __float2half_rn(v);
    __half ll = __float2half_rn(v - __half2float(hh));
    h = *reinterpret_cast<unsigned short*>(&hh);
    l = *reinterpret_cast<unsigned short*>(&ll);
}

// ---------------- degree / CSR build --------------------------------------------
__global__ void deg_init_kernel() {
    int i = blockIdx.x * blockDim.x + threadIdx.x;
    if (i < NN) g_cnt[i] = 0;
}
__global__ void deg_count_kernel(const int* __restrict__ dst) {
    int e = blockIdx.x * blockDim.x + threadIdx.x;
    if (e < EE) atomicAdd(&g_cnt[dst[e]], 1);
}
__global__ void deg_fin_kernel() {
    int i = blockIdx.x * blockDim.x + threadIdx.x;
    if (i < NN) g_deg[i] = rsqrtf((float)g_cnt[i] + 1.0f);
}
__global__ void scan1_kernel() {
    __shared__ int sc[256];
    int t = threadIdx.x;
    int i = blockIdx.x * 256 + t;
    int val = (i < NN) ? g_cnt[i] : 0;
    sc[t] = val;
    __syncthreads();
#pragma unroll
    for (int d = 1; d < 256; d <<= 1) {
        int v = (t >= d) ? sc[t - d] : 0;
        __syncthreads();
        sc[t] += v;
        __syncthreads();
    }
    if (i < NN) g_off[i] = sc[t] - val;
    if (t == 255) g_bsum[blockIdx.x] = sc[255];
}
__global__ void scan2_kernel() {
    __shared__ int sc[512];
    int t = threadIdx.x;
    int val = (t < 391) ? g_bsum[t] : 0;
    sc[t] = val;
    __syncthreads();
#pragma unroll
    for (int d = 1; d < 512; d <<= 1) {
        int v = (t >= d) ? sc[t - d] : 0;
        __syncthreads();
        sc[t] += v;
        __syncthreads();
    }
    if (t < 391) g_bsum[t] = sc[t] - val;
}
__global__ void scan3_kernel() {
    int i = blockIdx.x * blockDim.x + threadIdx.x;
    if (i < NN) {
        g_off[i] += g_bsum[i >> 8];
        g_fill[i] = 0;
    }
    if (i == 0) g_off[NN] = EE;
}
__global__ void fill_kernel(const int* __restrict__ src, const int* __restrict__ dst) {
    int e = blockIdx.x * blockDim.x + threadIdx.x;
    if (e >= EE) return;
    int d = dst[e];
    int pos = g_off[d] + atomicAdd(&g_fill[d], 1);
    g_csr[pos] = src[e];
}

// ---------------- W1 -> k-major fp16 split images -------------------------------
__global__ void w1cvt_kernel(const float* __restrict__ W1) {
    int t = blockIdx.x * blockDim.x + threadIdx.x;
    if (t >= 8192) return;
    int idx = t * 8;
    unsigned short h[8], l[8];
#pragma unroll
    for (int j = 0; j < 8; j++) hsplit(W1[idx + j], h[j], l[j]);
    reinterpret_cast<uint4*>(gW1h)[t] = make_uint4(
        (unsigned)h[0] | ((unsigned)h[1] << 16), (unsigned)h[2] | ((unsigned)h[3] << 16),
        (unsigned)h[4] | ((unsigned)h[5] << 16), (unsigned)h[6] | ((unsigned)h[7] << 16));
    reinterpret_cast<uint4*>(gW1l)[t] = make_uint4(
        (unsigned)l[0] | ((unsigned)l[1] << 16), (unsigned)l[2] | ((unsigned)l[3] << 16),
        (unsigned)l[4] | ((unsigned)l[5] << 16), (unsigned)l[6] | ((unsigned)l[7] << 16));
}

// ---------------- layer-1 aggregation: CSR gather -> fp16 A + threefry mask -----
__global__ __launch_bounds__(256) void agg1_gather_kernel(const float* __restrict__ x) {
    int n = blockIdx.x * 8 + (threadIdx.x >> 5);   // warp id = node (grid exact)
    int lane = threadIdx.x & 31;

    const float4* x4 = reinterpret_cast<const float4*>(x);
    float dn = g_deg[n];
    float4 xv = x4[n * 32 + lane];
    float s0 = dn * dn;
    float4 acc = make_float4(xv.x * s0, xv.y * s0, xv.z * s0, xv.w * s0);

    int beg = g_off[n], end = g_off[n + 1];
    for (int j = beg; j < end; j++) {
        int s = g_csr[j];
        float nrm = g_deg[s] * dn;
        float4 v = x4[s * 32 + lane];
        acc.x += nrm * v.x; acc.y += nrm * v.y;
        acc.z += nrm * v.z; acc.w += nrm * v.w;
    }
    // store A directly as fp16 (GEMM1 input)
    __half2 p0 = __floats2half2_rn(acc.x, acc.y);
    __half2 p1 = __floats2half2_rn(acc.z, acc.w);
    *reinterpret_cast<uint2*>(&gA16[n * 128 + lane * 4]) =
        make_uint2(*reinterpret_cast<unsigned*>(&p0), *reinterpret_cast<unsigned*>(&p1));

    // dropout mask for hidden row n (512 bits = 16 words)
    unsigned base = (unsigned)n * 512u + (unsigned)lane;
#pragma unroll
    for (int w = 0; w < 16; w++) {
        unsigned bit = tf_bit(base + (unsigned)w * 32u);
        unsigned word = __ballot_sync(0xFFFFFFFFu, bit);
        if (lane == 0) g_mask[n * 16 + w] = word;
    }
}

// ---------------- GEMM1 (mma.sync fp16 2-term): H = relu(A@W1+b1)*dropout ------
// A fp16 (pre-converted), W1 split fp16 hi/lo: D = A*Wh + A*Wl.
#define SROW 136
__global__ __launch_bounds__(256) void gemm1_mma_kernel(const float* __restrict__ bias,
                                                        float* __restrict__ H) {
    extern __shared__ char dsm[];
    __half* sA  = reinterpret_cast<__half*>(dsm);            // 34816B
    __half* sBh = reinterpret_cast<__half*>(dsm + 34816);    // 34816B
    __half* sBl = reinterpret_cast<__half*>(dsm + 69632);    // 34816B
    __shared__ float sBias[128];

    const int t = threadIdx.x;
    const int lane = t & 31, wid = t >> 5;
    const int m0 = blockIdx.x * 128;
    const int n0 = blockIdx.y * 128;

    if (t < 128) sBias[t] = bias[n0 + t];

    // B tiles (straight copy, 2048 uint4 each)
#pragma unroll
    for (int i = 0; i < 8; i++) {
        int c = i * 256 + t;
        int k = c >> 4, c8 = c & 15;
        uint4 vh = *reinterpret_cast<const uint4*>(&gW1h[k * 512 + n0 + c8 * 8]);
        uint4 vl = *reinterpret_cast<const uint4*>(&gW1l[k * 512 + n0 + c8 * 8]);
        *reinterpret_cast<uint4*>(&sBh[k * SROW + c8 * 8]) = vh;
        *reinterpret_cast<uint4*>(&sBl[k * SROW + c8 * 8]) = vl;
    }
    // A tile (straight fp16 copy, 2048 uint4)
#pragma unroll
    for (int i = 0; i < 8; i++) {
        int c = i * 256 + t;
        int m = c >> 4, c8 = c & 15;
        int gr = m0 + m;
        uint4 v = make_uint4(0u, 0u, 0u, 0u);
        if (gr < NN) v = *reinterpret_cast<const uint4*>(&gA16[gr * 128 + c8 * 8]);
        *reinterpret_cast<uint4*>(&sA[m * SROW + c8 * 8]) = v;
    }
    __syncthreads();

    const int wm = wid & 3;
    const int wn = wid >> 2;
    float acc[2][8][4];
#pragma unroll
    for (int mf = 0; mf < 2; mf++)
#pragma unroll
        for (int nf = 0; nf < 8; nf++)
#pragma unroll
            for (int q = 0; q < 4; q++) acc[mf][nf][q] = 0.f;

    const unsigned aBase = smem_u32(sA) +
        ((unsigned)(wm * 32 + (lane & 15)) * SROW + (unsigned)((lane >> 4) * 8)) * 2u;
    const unsigned bBaseH = smem_u32(sBh) +
        ((unsigned)(lane & 15) * SROW + (unsigned)(wn * 64 + ((lane >> 4) << 3))) * 2u;
    const unsigned bBaseL = bBaseH + 34816u;

#pragma unroll
    for (int ks = 0; ks < 8; ks++) {
        unsigned ah[2][4], bh[4][4], bl[4][4];
#pragma unroll
        for (int mf = 0; mf < 2; mf++)
            ldsm_x4(ah[mf], aBase + (unsigned)(mf * 16 * SROW * 2) + (unsigned)(ks * 32));
#pragma unroll
        for (int j = 0; j < 4; j++) {
            ldsm_x4t(bh[j], bBaseH + (unsigned)(ks * 16 * SROW * 2) + (unsigned)(j * 32));
            ldsm_x4t(bl[j], bBaseL + (unsigned)(ks * 16 * SROW * 2) + (unsigned)(j * 32));
        }
#pragma unroll
        for (int mf = 0; mf < 2; mf++) {
#pragma unroll
            for (int j = 0; j < 4; j++) {
                mma_f16(acc[mf][2 * j],     ah[mf], bh[j][0], bh[j][1]);
                mma_f16(acc[mf][2 * j],     ah[mf], bl[j][0], bl[j][1]);
                mma_f16(acc[mf][2 * j + 1], ah[mf], bh[j][2], bh[j][3]);
                mma_f16(acc[mf][2 * j + 1], ah[mf], bl[j][2], bl[j][3]);
            }
        }
    }

    const int quad = lane >> 2, qt = lane & 3;
#pragma unroll
    for (int mf = 0; mf < 2; mf++) {
#pragma unroll
        for (int p = 0; p < 2; p++) {
            int row = m0 + wm * 32 + mf * 16 + quad + p * 8;
            if (row >= NN) continue;
            unsigned mw0 = g_mask[row * 16 + ((n0 + wn * 64) >> 5)];
            unsigned mw1 = g_mask[row * 16 + ((n0 + wn * 64) >> 5) + 1];
            float* hp = H + (size_t)row * 512 + n0 + wn * 64;
#pragma unroll
            for (int nf = 0; nf < 8; nf++) {
                int cl = nf * 8 + qt * 2;
                unsigned mw = (cl < 32) ? mw0 : mw1;
                int sh = cl & 31;
                float v0 = fmaxf(acc[mf][nf][p * 2 + 0] + sBias[wn * 64 + cl + 0], 0.f) * 2.f;
                float v1 = fmaxf(acc[mf][nf][p * 2 + 1] + sBias[wn * 64 + cl + 1], 0.f) * 2.f;
                float2 o;
                o.x = ((mw >> (sh + 0)) & 1u) ? v0 : 0.f;
                o.y = ((mw >> (sh + 1)) & 1u) ? v1 : 0.f;
                *reinterpret_cast<float2*>(hp + cl) = o;
            }
        }
    }
}

// ---------------- GEMM2 (FFMA2): g_h2 = H @ W2 ----------------------------------
__global__ __launch_bounds__(256) void gemm2_kernel(const float* __restrict__ H,
                                                    const float* __restrict__ W2) {
    __shared__ __align__(16) float As[32][260];
    __shared__ __align__(16) float Ws[32][40];
    const int t = threadIdx.x;
    const int rg = t & 63;
    const int cg = t >> 6;
    const int m0 = blockIdx.x * 256;

    unsigned long long acc[4][5];
#pragma unroll
    for (int i = 0; i < 4; i++)
#pragma unroll
        for (int j = 0; j < 5; j++) acc[i][j] = 0ull;

    const int akq = t & 7;
    const int am = t >> 3;

    for (int kc = 0; kc < 16; kc++) {
#pragma unroll
        for (int p = 0; p < 8; p++) {
            int m = p * 32 + am;
            int gr = m0 + m;
            float4 v = make_float4(0.f, 0.f, 0.f, 0.f);
            if (gr < NN)
                v = *reinterpret_cast<const float4*>(&H[gr * 512 + kc * 32 + akq * 4]);
            As[akq * 4 + 0][m] = v.x;
            As[akq * 4 + 1][m] = v.y;
            As[akq * 4 + 2][m] = v.z;
            As[akq * 4 + 3][m] = v.w;
        }
#pragma unroll
        for (int p = 0; p < 2; p++) {
            int idx = p * 256 + t;
            if (idx < 320) {
                int k = idx / 10, c = idx % 10;
                *reinterpret_cast<float4*>(&Ws[k][c * 4]) =
                    *reinterpret_cast<const float4*>(&W2[(kc * 32 + k) * 40 + c * 4]);
            }
        }
        __syncthreads();
#pragma unroll
        for (int k = 0; k < 32; k++) {
            float4 a = *reinterpret_cast<const float4*>(&As[k][rg * 4]);
            const float* wr = &Ws[k][cg * 10];
            unsigned long long w0 = *reinterpret_cast<const unsigned long long*>(wr + 0);
            unsigned long long w1 = *reinterpret_cast<const unsigned long long*>(wr + 2);
            unsigned long long w2 = *reinterpret_cast<const unsigned long long*>(wr + 4);
            unsigned long long w3 = *reinterpret_cast<const unsigned long long*>(wr + 6);
            unsigned long long w4 = *reinterpret_cast<const unsigned long long*>(wr + 8);
            float av[4] = {a.x, a.y, a.z, a.w};
#pragma unroll
            for (int i = 0; i < 4; i++) {
                unsigned long long ai = pack2(av[i], av[i]);
                acc[i][0] = fma2(ai, w0, acc[i][0]);
                acc[i][1] = fma2(ai, w1, acc[i][1]);
                acc[i][2] = fma2(ai, w2, acc[i][2]);
                acc[i][3] = fma2(ai, w3, acc[i][3]);
                acc[i][4] = fma2(ai, w4, acc[i][4]);
            }
        }
        __syncthreads();
    }
#pragma unroll
    for (int i = 0; i < 4; i++) {
        int row = m0 + rg * 4 + i;
        if (row >= NN) continue;
#pragma unroll
        for (int j = 0; j < 5; j++)
            *reinterpret_cast<unsigned long long*>(&g_h2[row * 40 + cg * 10 + j * 2]) = acc[i][j];
    }
}

// ---------------- layer-2 aggregation: CSR gather -------------------------------
// One warp per node. Lane groups 0-9 / 10-19 / 20-29 process neighbors j, j+1, j+2
// (each group covers the 10 float4 columns of a row); shfl-reduce, add b2, store.
__global__ __launch_bounds__(256) void agg2_gather_kernel(const float* __restrict__ b2,
                                                          float* __restrict__ out) {
    int n = blockIdx.x * 8 + (threadIdx.x >> 5);   // grid exact: 12500*8 = NN
    int lane = threadIdx.x & 31;
    int grp = lane >= 30 ? 3 : lane / 10;
    int cl = lane - grp * 10;
    bool act = lane < 30;

    const float4* h4 = reinterpret_cast<const float4*>(g_h2);
    float dn = g_deg[n];
    float4 acc = make_float4(0.f, 0.f, 0.f, 0.f);
    if (grp == 0) {                                // self term
        float4 v = h4[n * 10 + cl];
        float s0 = dn * dn;
        acc = make_float4(v.x * s0, v.y * s0, v.z * s0, v.w * s0);
    }
    int beg = g_off[n], end = g_off[n + 1];
    for (int j = beg + grp; j < end; j += 3) {
        if (act) {
            int s = g_csr[j];
            float nrm = g_deg[s] * dn;
            float4 v = h4[s * 10 + cl];
            acc.x += nrm * v.x; acc.y += nrm * v.y;
            acc.z += nrm * v.z; acc.w += nrm * v.w;
        }
    }
    const unsigned FULL = 0xFFFFFFFFu;
    acc.x += __shfl_down_sync(FULL, acc.x, 10) + __shfl_down_sync(FULL, acc.x, 20);
    acc.y += __shfl_down_sync(FULL, acc.y, 10) + __shfl_down_sync(FULL, acc.y, 20);
    acc.z += __shfl_down_sync(FULL, acc.z, 10) + __shfl_down_sync(FULL, acc.z, 20);
    acc.w += __shfl_down_sync(FULL, acc.w, 10) + __shfl_down_sync(FULL, acc.w, 20);
    if (lane < 10) {
        float4 bb = *reinterpret_cast<const float4*>(&b2[cl * 4]);
        *reinterpret_cast<float4*>(&out[n * 40 + cl * 4]) =
            make_float4(acc.x + bb.x, acc.y + bb.y, acc.z + bb.z, acc.w + bb.w);
    }
}

// ---------------- launch --------------------------------------------------------
extern "C" void kernel_launch(void* const* d_in, const int* in_sizes, int n_in,
                              void* d_out, int out_size) {
    const float* x  = (const float*)d_in[0];
    const int*   ei = (const int*)d_in[1];
    const float* W1 = (const float*)d_in[2];
    const float* b1 = (const float*)d_in[3];
    const float* W2 = (const float*)d_in[4];
    const float* b2 = (const float*)d_in[5];
    (void)in_sizes; (void)n_in; (void)out_size;

    float* out = (float*)d_out;           // [NN, 40]
    float* hidden = out + NN * 40;        // [NN, 512]
    const int* src = ei;
    const int* dst = ei + EE;

    const int GEMM1_SMEM = 104448;        // A + Bh + Bl fp16 tiles
    cudaFuncSetAttribute(gemm1_mma_kernel,
                         cudaFuncAttributeMaxDynamicSharedMemorySize, GEMM1_SMEM);

    // degree + CSR build
    deg_init_kernel<<<(NN + 255) / 256, 256>>>();
    deg_count_kernel<<<(EE + 255) / 256, 256>>>(dst);
    deg_fin_kernel<<<(NN + 255) / 256, 256>>>();
    scan1_kernel<<<391, 256>>>();
    scan2_kernel<<<1, 512>>>();
    scan3_kernel<<<(NN + 255) / 256, 256>>>();
    fill_kernel<<<(EE + 255) / 256, 256>>>(src, dst);

    w1cvt_kernel<<<32, 256>>>(W1);

    // layer-1 aggregation (gather) -> fp16 A + fused dropout mask
    agg1_gather_kernel<<<12500, 256>>>(x);

    gemm1_mma_kernel<<<dim3((NN + 127) / 128, 4), 256, GEMM1_SMEM>>>(b1, hidden);
    gemm2_kernel<<<(NN + 255) / 256, 256>>>(hidden, W2);

    // layer-2 aggregation (gather) + fused b2
    agg2_gather_kernel<<<12500, 256>>>(b2, out);
}

// round 10
// speedup vs baseline: 1.7408x; 1.0388x over previous
#include <cuda_runtime.h>
#include <cuda_fp16.h>
#include <cstdint>

#define NN 100000
#define EE 800000

// ---------------- scratch (__device__ globals; no allocation allowed) ----------
__device__ float g_deg[NN];                       // dinv_sqrt
__device__ int   g_cnt[NN];                       // in-degree counts
__device__ int   g_off[NN + 1];                   // CSR offsets (by dst)
__device__ int   g_fill[NN];                      // fill cursors
__device__ int   g_csr[EE];                       // src ids grouped by dst
__device__ int   g_bsum[512];                     // scan block sums
__device__ __align__(16) __half gA16[NN * 128];   // aggregated X, fp16 (GEMM1 A)
__device__ __align__(16) float g_h2[NN * 40];     // hidden @ W2 (pre-aggregation)
__device__ unsigned g_mask[1600000];              // 51.2M dropout keep-bits
// k-major fp16 image of W1: [k=128][n=512]
__device__ __align__(16) __half gW1h[128 * 512];

// ---------------- small helpers ------------------------------------------------
__device__ __forceinline__ unsigned long long pack2(float x, float y) {
    unsigned long long r;
    asm("mov.b64 %0, {%1, %2};" : "=l"(r) : "f"(x), "f"(y));
    return r;
}
__device__ __forceinline__ unsigned long long fma2(unsigned long long a,
                                                   unsigned long long b,
                                                   unsigned long long c) {
    unsigned long long d;
    asm("fma.rn.f32x2 %0, %1, %2, %3;" : "=l"(d) : "l"(a), "l"(b), "l"(c));
    return d;
}
__device__ __forceinline__ unsigned smem_u32(const void* p) {
    unsigned a;
    asm("{ .reg .u64 t; cvta.to.shared.u64 t, %1; cvt.u32.u64 %0, t; }" : "=r"(a) : "l"(p));
    return a;
}

// JAX threefry2x32 with key = (0, 42)
__device__ __forceinline__ void threefry42(unsigned& x0, unsigned& x1) {
    const unsigned ks0 = 0u, ks1 = 42u, ks2 = 0x1BD11BDAu ^ 42u;
    x0 += ks0; x1 += ks1;
#define TFR(r) { x0 += x1; x1 = (x1 << (r)) | (x1 >> (32 - (r))); x1 ^= x0; }
    TFR(13) TFR(15) TFR(26) TFR(6)   x0 += ks1; x1 += ks2 + 1u;
    TFR(17) TFR(29) TFR(16) TFR(24)  x0 += ks2; x1 += ks0 + 2u;
    TFR(13) TFR(15) TFR(26) TFR(6)   x0 += ks0; x1 += ks1 + 3u;
    TFR(17) TFR(29) TFR(16) TFR(24)  x0 += ks1; x1 += ks2 + 4u;
    TFR(13) TFR(15) TFR(26) TFR(6)   x0 += ks2; x1 += ks0 + 5u;
#undef TFR
}
__device__ __forceinline__ unsigned tf_bit(unsigned idx) {
    unsigned x0 = 0u, x1 = idx;
    threefry42(x0, x1);
    return (~(x0 ^ x1)) >> 31;
}

// ---------------- mma.sync / ldmatrix wrappers ----------------------------------
__device__ __forceinline__ void mma_f16(float* c, const unsigned* a, unsigned b0, unsigned b1) {
    asm volatile(
        "mma.sync.aligned.m16n8k16.row.col.f32.f16.f16.f32 "
        "{%0,%1,%2,%3}, {%4,%5,%6,%7}, {%8,%9}, {%0,%1,%2,%3};"
        : "+f"(c[0]), "+f"(c[1]), "+f"(c[2]), "+f"(c[3])
        : "r"(a[0]), "r"(a[1]), "r"(a[2]), "r"(a[3]), "r"(b0), "r"(b1));
}
__device__ __forceinline__ void ldsm_x4(unsigned* r, unsigned addr) {
    asm volatile("ldmatrix.sync.aligned.m8n8.x4.shared.b16 {%0,%1,%2,%3}, [%4];"
                 : "=r"(r[0]), "=r"(r[1]), "=r"(r[2]), "=r"(r[3]) : "r"(addr));
}
__device__ __forceinline__ void ldsm_x4t(unsigned* r, unsigned addr) {
    asm volatile("ldmatrix.sync.aligned.m8n8.x4.trans.shared.b16 {%0,%1,%2,%3}, [%4];"
                 : "=r"(r[0]), "=r"(r[1]), "=r"(r[2]), "=r"(r[3]) : "r"(addr));
}

// ---------------- degree / CSR build --------------------------------------------
__global__ void deg_init_kernel() {
    int i = blockIdx.x * blockDim.x + threadIdx.x;
    if (i < NN) g_cnt[i] = 0;
}
__global__ void deg_count_kernel(const int* __restrict__ dst) {
    int e = blockIdx.x * blockDim.x + threadIdx.x;
    if (e < EE) atomicAdd(&g_cnt[dst[e]], 1);
}
__global__ void deg_fin_kernel() {
    int i = blockIdx.x * blockDim.x + threadIdx.x;
    if (i < NN) g_deg[i] = rsqrtf((float)g_cnt[i] + 1.0f);
}
__global__ void scan1_kernel() {
    __shared__ int sc[256];
    int t = threadIdx.x;
    int i = blockIdx.x * 256 + t;
    int val = (i < NN) ? g_cnt[i] : 0;
    sc[t] = val;
    __syncthreads();
#pragma unroll
    for (int d = 1; d < 256; d <<= 1) {
        int v = (t >= d) ? sc[t - d] : 0;
        __syncthreads();
        sc[t] += v;
        __syncthreads();
    }
    if (i < NN) g_off[i] = sc[t] - val;
    if (t == 255) g_bsum[blockIdx.x] = sc[255];
}
__global__ void scan2_kernel() {
    __shared__ int sc[512];
    int t = threadIdx.x;
    int val = (t < 391) ? g_bsum[t] : 0;
    sc[t] = val;
    __syncthreads();
#pragma unroll
    for (int d = 1; d < 512; d <<= 1) {
        int v = (t >= d) ? sc[t - d] : 0;
        __syncthreads();
        sc[t] += v;
        __syncthreads();
    }
    if (t < 391) g_bsum[t] = sc[t] - val;
}
__global__ void scan3_kernel() {
    int i = blockIdx.x * blockDim.x + threadIdx.x;
    if (i < NN) {
        g_off[i] += g_bsum[i >> 8];
        g_fill[i] = 0;
    }
    if (i == 0) g_off[NN] = EE;
}
__global__ void fill_kernel(const int* __restrict__ src, const int* __restrict__ dst) {
    int e = blockIdx.x * blockDim.x + threadIdx.x;
    if (e >= EE) return;
    int d = dst[e];
    int pos = g_off[d] + atomicAdd(&g_fill[d], 1);
    g_csr[pos] = src[e];
}

// ---------------- W1 -> k-major fp16 image --------------------------------------
__global__ void w1cvt_kernel(const float* __restrict__ W1) {
    int t = blockIdx.x * blockDim.x + threadIdx.x;
    if (t >= 8192) return;
    int idx = t * 8;
    unsigned short h[8];
#pragma unroll
    for (int j = 0; j < 8; j++) {
        __half hh = __float2half_rn(W1[idx + j]);
        h[j] = *reinterpret_cast<unsigned short*>(&hh);
    }
    reinterpret_cast<uint4*>(gW1h)[t] = make_uint4(
        (unsigned)h[0] | ((unsigned)h[1] << 16), (unsigned)h[2] | ((unsigned)h[3] << 16),
        (unsigned)h[4] | ((unsigned)h[5] << 16), (unsigned)h[6] | ((unsigned)h[7] << 16));
}

// ---------------- layer-1 aggregation: CSR gather (MLP=4) -> fp16 A + mask ------
__global__ __launch_bounds__(256) void agg1_gather_kernel(const float* __restrict__ x) {
    int n = blockIdx.x * 8 + (threadIdx.x >> 5);   // warp id = node (grid exact)
    int lane = threadIdx.x & 31;

    const float4* x4 = reinterpret_cast<const float4*>(x);
    float dn = g_deg[n];
    float4 xv = x4[n * 32 + lane];
    float s0 = dn * dn;
    float4 acc = make_float4(xv.x * s0, xv.y * s0, xv.z * s0, xv.w * s0);

    int beg = g_off[n], end = g_off[n + 1];
    int j = beg;
    // unrolled by 4: batch indices + degs, then 4 independent gathers in flight
    for (; j + 4 <= end; j += 4) {
        int i0 = g_csr[j], i1 = g_csr[j + 1], i2 = g_csr[j + 2], i3 = g_csr[j + 3];
        float n0 = g_deg[i0] * dn, n1 = g_deg[i1] * dn;
        float n2 = g_deg[i2] * dn, n3 = g_deg[i3] * dn;
        float4 v0 = x4[i0 * 32 + lane];
        float4 v1 = x4[i1 * 32 + lane];
        float4 v2 = x4[i2 * 32 + lane];
        float4 v3 = x4[i3 * 32 + lane];
        acc.x += n0 * v0.x + n1 * v1.x + n2 * v2.x + n3 * v3.x;
        acc.y += n0 * v0.y + n1 * v1.y + n2 * v2.y + n3 * v3.y;
        acc.z += n0 * v0.z + n1 * v1.z + n2 * v2.z + n3 * v3.z;
        acc.w += n0 * v0.w + n1 * v1.w + n2 * v2.w + n3 * v3.w;
    }
    for (; j < end; j++) {
        int s = g_csr[j];
        float nrm = g_deg[s] * dn;
        float4 v = x4[s * 32 + lane];
        acc.x += nrm * v.x; acc.y += nrm * v.y;
        acc.z += nrm * v.z; acc.w += nrm * v.w;
    }
    __half2 p0 = __floats2half2_rn(acc.x, acc.y);
    __half2 p1 = __floats2half2_rn(acc.z, acc.w);
    *reinterpret_cast<uint2*>(&gA16[n * 128 + lane * 4]) =
        make_uint2(*reinterpret_cast<unsigned*>(&p0), *reinterpret_cast<unsigned*>(&p1));

    // dropout mask for hidden row n (512 bits = 16 words)
    unsigned base = (unsigned)n * 512u + (unsigned)lane;
#pragma unroll
    for (int w = 0; w < 16; w++) {
        unsigned bit = tf_bit(base + (unsigned)w * 32u);
        unsigned word = __ballot_sync(0xFFFFFFFFu, bit);
        if (lane == 0) g_mask[n * 16 + w] = word;
    }
}

// ---------------- GEMM1 (mma.sync fp16): H = relu(A@W1+b1)*dropout -------------
#define SROW 136
__global__ __launch_bounds__(256) void gemm1_mma_kernel(const float* __restrict__ bias,
                                                        float* __restrict__ H) {
    extern __shared__ char dsm[];
    __half* sA = reinterpret_cast<__half*>(dsm);            // 34816B
    __half* sB = reinterpret_cast<__half*>(dsm + 34816);    // 34816B
    __shared__ float sBias[128];

    const int t = threadIdx.x;
    const int lane = t & 31, wid = t >> 5;
    const int m0 = blockIdx.x * 128;
    const int n0 = blockIdx.y * 128;

    if (t < 128) sBias[t] = bias[n0 + t];

    // B tile (straight copy, 2048 uint4)
#pragma unroll
    for (int i = 0; i < 8; i++) {
        int c = i * 256 + t;
        int k = c >> 4, c8 = c & 15;
        uint4 v = *reinterpret_cast<const uint4*>(&gW1h[k * 512 + n0 + c8 * 8]);
        *reinterpret_cast<uint4*>(&sB[k * SROW + c8 * 8]) = v;
    }
    // A tile (straight fp16 copy, 2048 uint4)
#pragma unroll
    for (int i = 0; i < 8; i++) {
        int c = i * 256 + t;
        int m = c >> 4, c8 = c & 15;
        int gr = m0 + m;
        uint4 v = make_uint4(0u, 0u, 0u, 0u);
        if (gr < NN) v = *reinterpret_cast<const uint4*>(&gA16[gr * 128 + c8 * 8]);
        *reinterpret_cast<uint4*>(&sA[m * SROW + c8 * 8]) = v;
    }
    __syncthreads();

    const int wm = wid & 3;
    const int wn = wid >> 2;
    float acc[2][8][4];
#pragma unroll
    for (int mf = 0; mf < 2; mf++)
#pragma unroll
        for (int nf = 0; nf < 8; nf++)
#pragma unroll
            for (int q = 0; q < 4; q++) acc[mf][nf][q] = 0.f;

    const unsigned aBase = smem_u32(sA) +
        ((unsigned)(wm * 32 + (lane & 15)) * SROW + (unsigned)((lane >> 4) * 8)) * 2u;
    const unsigned bBase = smem_u32(sB) +
        ((unsigned)(lane & 15) * SROW + (unsigned)(wn * 64 + ((lane >> 4) << 3))) * 2u;

#pragma unroll
    for (int ks = 0; ks < 8; ks++) {
        unsigned ah[2][4], bh[4][4];
#pragma unroll
        for (int mf = 0; mf < 2; mf++)
            ldsm_x4(ah[mf], aBase + (unsigned)(mf * 16 * SROW * 2) + (unsigned)(ks * 32));
#pragma unroll
        for (int j = 0; j < 4; j++)
            ldsm_x4t(bh[j], bBase + (unsigned)(ks * 16 * SROW * 2) + (unsigned)(j * 32));
#pragma unroll
        for (int mf = 0; mf < 2; mf++) {
#pragma unroll
            for (int j = 0; j < 4; j++) {
                mma_f16(acc[mf][2 * j],     ah[mf], bh[j][0], bh[j][1]);
                mma_f16(acc[mf][2 * j + 1], ah[mf], bh[j][2], bh[j][3]);
            }
        }
    }

    const int quad = lane >> 2, qt = lane & 3;
#pragma unroll
    for (int mf = 0; mf < 2; mf++) {
#pragma unroll
        for (int p = 0; p < 2; p++) {
            int row = m0 + wm * 32 + mf * 16 + quad + p * 8;
            if (row >= NN) continue;
            unsigned mw0 = g_mask[row * 16 + ((n0 + wn * 64) >> 5)];
            unsigned mw1 = g_mask[row * 16 + ((n0 + wn * 64) >> 5) + 1];
            float* hp = H + (size_t)row * 512 + n0 + wn * 64;
#pragma unroll
            for (int nf = 0; nf < 8; nf++) {
                int cl = nf * 8 + qt * 2;
                unsigned mw = (cl < 32) ? mw0 : mw1;
                int sh = cl & 31;
                float v0 = fmaxf(acc[mf][nf][p * 2 + 0] + sBias[wn * 64 + cl + 0], 0.f) * 2.f;
                float v1 = fmaxf(acc[mf][nf][p * 2 + 1] + sBias[wn * 64 + cl + 1], 0.f) * 2.f;
                float2 o;
                o.x = ((mw >> (sh + 0)) & 1u) ? v0 : 0.f;
                o.y = ((mw >> (sh + 1)) & 1u) ? v1 : 0.f;
                *reinterpret_cast<float2*>(hp + cl) = o;
            }
        }
    }
}

// ---------------- GEMM2 (FFMA2): g_h2 = H @ W2 ----------------------------------
__global__ __launch_bounds__(256) void gemm2_kernel(const float* __restrict__ H,
                                                    const float* __restrict__ W2) {
    __shared__ __align__(16) float As[32][260];
    __shared__ __align__(16) float Ws[32][40];
    const int t = threadIdx.x;
    const int rg = t & 63;
    const int cg = t >> 6;
    const int m0 = blockIdx.x * 256;

    unsigned long long acc[4][5];
#pragma unroll
    for (int i = 0; i < 4; i++)
#pragma unroll
        for (int j = 0; j < 5; j++) acc[i][j] = 0ull;

    const int akq = t & 7;
    const int am = t >> 3;

    for (int kc = 0; kc < 16; kc++) {
#pragma unroll
        for (int p = 0; p < 8; p++) {
            int m = p * 32 + am;
            int gr = m0 + m;
            float4 v = make_float4(0.f, 0.f, 0.f, 0.f);
            if (gr < NN)
                v = *reinterpret_cast<const float4*>(&H[gr * 512 + kc * 32 + akq * 4]);
            As[akq * 4 + 0][m] = v.x;
            As[akq * 4 + 1][m] = v.y;
            As[akq * 4 + 2][m] = v.z;
            As[akq * 4 + 3][m] = v.w;
        }
#pragma unroll
        for (int p = 0; p < 2; p++) {
            int idx = p * 256 + t;
            if (idx < 320) {
                int k = idx / 10, c = idx % 10;
                *reinterpret_cast<float4*>(&Ws[k][c * 4]) =
                    *reinterpret_cast<const float4*>(&W2[(kc * 32 + k) * 40 + c * 4]);
            }
        }
        __syncthreads();
#pragma unroll
        for (int k = 0; k < 32; k++) {
            float4 a = *reinterpret_cast<const float4*>(&As[k][rg * 4]);
            const float* wr = &Ws[k][cg * 10];
            unsigned long long w0 = *reinterpret_cast<const unsigned long long*>(wr + 0);
            unsigned long long w1 = *reinterpret_cast<const unsigned long long*>(wr + 2);
            unsigned long long w2 = *reinterpret_cast<const unsigned long long*>(wr + 4);
            unsigned long long w3 = *reinterpret_cast<const unsigned long long*>(wr + 6);
            unsigned long long w4 = *reinterpret_cast<const unsigned long long*>(wr + 8);
            float av[4] = {a.x, a.y, a.z, a.w};
#pragma unroll
            for (int i = 0; i < 4; i++) {
                unsigned long long ai = pack2(av[i], av[i]);
                acc[i][0] = fma2(ai, w0, acc[i][0]);
                acc[i][1] = fma2(ai, w1, acc[i][1]);
                acc[i][2] = fma2(ai, w2, acc[i][2]);
                acc[i][3] = fma2(ai, w3, acc[i][3]);
                acc[i][4] = fma2(ai, w4, acc[i][4]);
            }
        }
        __syncthreads();
    }
#pragma unroll
    for (int i = 0; i < 4; i++) {
        int row = m0 + rg * 4 + i;
        if (row >= NN) continue;
#pragma unroll
        for (int j = 0; j < 5; j++)
            *reinterpret_cast<unsigned long long*>(&g_h2[row * 40 + cg * 10 + j * 2]) = acc[i][j];
    }
}

// ---------------- layer-2 aggregation: CSR gather (unroll 2) --------------------
__global__ __launch_bounds__(256) void agg2_gather_kernel(const float* __restrict__ b2,
                                                          float* __restrict__ out) {
    int n = blockIdx.x * 8 + (threadIdx.x >> 5);   // grid exact: 12500*8 = NN
    int lane = threadIdx.x & 31;
    int grp = lane >= 30 ? 3 : lane / 10;
    int cl = lane - grp * 10;
    bool act = lane < 30;

    const float4* h4 = reinterpret_cast<const float4*>(g_h2);
    float dn = g_deg[n];
    float4 acc = make_float4(0.f, 0.f, 0.f, 0.f);
    if (grp == 0) {                                // self term
        float4 v = h4[n * 10 + cl];
        float s0 = dn * dn;
        acc = make_float4(v.x * s0, v.y * s0, v.z * s0, v.w * s0);
    }
    int beg = g_off[n], end = g_off[n + 1];
    int j = beg + grp;
    if (act) {
        for (; j + 3 < end; j += 6) {              // 2 iters in flight per group
            int s0i = g_csr[j], s1i = g_csr[j + 3];
            float n0 = g_deg[s0i] * dn, n1 = g_deg[s1i] * dn;
            float4 v0 = h4[s0i * 10 + cl];
            float4 v1 = h4[s1i * 10 + cl];
            acc.x += n0 * v0.x + n1 * v1.x;
            acc.y += n0 * v0.y + n1 * v1.y;
            acc.z += n0 * v0.z + n1 * v1.z;
            acc.w += n0 * v0.w + n1 * v1.w;
        }
        for (; j < end; j += 3) {
            int s = g_csr[j];
            float nrm = g_deg[s] * dn;
            float4 v = h4[s * 10 + cl];
            acc.x += nrm * v.x; acc.y += nrm * v.y;
            acc.z += nrm * v.z; acc.w += nrm * v.w;
        }
    }
    const unsigned FULL = 0xFFFFFFFFu;
    acc.x += __shfl_down_sync(FULL, acc.x, 10) + __shfl_down_sync(FULL, acc.x, 20);
    acc.y += __shfl_down_sync(FULL, acc.y, 10) + __shfl_down_sync(FULL, acc.y, 20);
    acc.z += __shfl_down_sync(FULL, acc.z, 10) + __shfl_down_sync(FULL, acc.z, 20);
    acc.w += __shfl_down_sync(FULL, acc.w, 10) + __shfl_down_sync(FULL, acc.w, 20);
    if (lane < 10) {
        float4 bb = *reinterpret_cast<const float4*>(&b2[cl * 4]);
        *reinterpret_cast<float4*>(&out[n * 40 + cl * 4]) =
            make_float4(acc.x + bb.x, acc.y + bb.y, acc.z + bb.z, acc.w + bb.w);
    }
}

// ---------------- launch --------------------------------------------------------
extern "C" void kernel_launch(void* const* d_in, const int* in_sizes, int n_in,
                              void* d_out, int out_size) {
    const float* x  = (const float*)d_in[0];
    const int*   ei = (const int*)d_in[1];
    const float* W1 = (const float*)d_in[2];
    const float* b1 = (const float*)d_in[3];
    const float* W2 = (const float*)d_in[4];
    const float* b2 = (const float*)d_in[5];
    (void)in_sizes; (void)n_in; (void)out_size;

    float* out = (float*)d_out;           // [NN, 40]
    float* hidden = out + NN * 40;        // [NN, 512]
    const int* src = ei;
    const int* dst = ei + EE;

    const int GEMM1_SMEM = 69632;         // A + B fp16 tiles (2 CTAs/SM)
    cudaFuncSetAttribute(gemm1_mma_kernel,
                         cudaFuncAttributeMaxDynamicSharedMemorySize, GEMM1_SMEM);

    // degree + CSR build
    deg_init_kernel<<<(NN + 255) / 256, 256>>>();
    deg_count_kernel<<<(EE + 255) / 256, 256>>>(dst);
    deg_fin_kernel<<<(NN + 255) / 256, 256>>>();
    scan1_kernel<<<391, 256>>>();
    scan2_kernel<<<1, 512>>>();
    scan3_kernel<<<(NN + 255) / 256, 256>>>();
    fill_kernel<<<(EE + 255) / 256, 256>>>(src, dst);

    w1cvt_kernel<<<32, 256>>>(W1);

    // layer-1 aggregation (gather, MLP=4) -> fp16 A + fused dropout mask
    agg1_gather_kernel<<<12500, 256>>>(x);

    gemm1_mma_kernel<<<dim3((NN + 127) / 128, 4), 256, GEMM1_SMEM>>>(b1, hidden);
    gemm2_kernel<<<(NN + 255) / 256, 256>>>(hidden, W2);

    // layer-2 aggregation (gather, unroll 2) + fused b2
    agg2_gather_kernel<<<12500, 256>>>(b2, out);
}

// round 11
// speedup vs baseline: 1.8606x; 1.0688x over previous
#include <cuda_runtime.h>
#include <cuda_fp16.h>
#include <cstdint>

#define NN 100000
#define EE 800000

// ---------------- scratch (__device__ globals; no allocation allowed) ----------
__device__ float g_deg[NN];                       // dinv_sqrt
__device__ int   g_cnt[NN];                       // in-degree counts
__device__ int   g_off[NN + 1];                   // CSR offsets (by dst)
__device__ int   g_fill[NN];                      // fill cursors
__device__ int   g_csr[EE];                       // src ids grouped by dst
__device__ int   g_bsum[512];                     // scan block sums
__device__ __align__(16) __half gX16[NN * 128];   // x in fp16 (agg1 gather source)
__device__ __align__(16) __half gA16[NN * 128];   // aggregated X, fp16 (GEMM1 A)
__device__ __align__(16) __half gH16[NN * 512];   // hidden in fp16 (GEMM2 A)
__device__ __align__(16) float g_h2[NN * 40];     // hidden @ W2 (pre-aggregation)
__device__ unsigned g_mask[1600000];              // 51.2M dropout keep-bits
__device__ __align__(16) __half gW1h[128 * 512];  // W1 fp16, k-major
__device__ __align__(16) __half gW2h[512 * 40];   // W2 fp16, k-major

// ---------------- small helpers ------------------------------------------------
__device__ __forceinline__ unsigned smem_u32(const void* p) {
    unsigned a;
    asm("{ .reg .u64 t; cvta.to.shared.u64 t, %1; cvt.u32.u64 %0, t; }" : "=r"(a) : "l"(p));
    return a;
}

// JAX threefry2x32 with key = (0, 42)
__device__ __forceinline__ void threefry42(unsigned& x0, unsigned& x1) {
    const unsigned ks0 = 0u, ks1 = 42u, ks2 = 0x1BD11BDAu ^ 42u;
    x0 += ks0; x1 += ks1;
#define TFR(r) { x0 += x1; x1 = (x1 << (r)) | (x1 >> (32 - (r))); x1 ^= x0; }
    TFR(13) TFR(15) TFR(26) TFR(6)   x0 += ks1; x1 += ks2 + 1u;
    TFR(17) TFR(29) TFR(16) TFR(24)  x0 += ks2; x1 += ks0 + 2u;
    TFR(13) TFR(15) TFR(26) TFR(6)   x0 += ks0; x1 += ks1 + 3u;
    TFR(17) TFR(29) TFR(16) TFR(24)  x0 += ks1; x1 += ks2 + 4u;
    TFR(13) TFR(15) TFR(26) TFR(6)   x0 += ks2; x1 += ks0 + 5u;
#undef TFR
}
__device__ __forceinline__ unsigned tf_bit(unsigned idx) {
    unsigned x0 = 0u, x1 = idx;
    threefry42(x0, x1);
    return (~(x0 ^ x1)) >> 31;
}

// ---------------- mma.sync / ldmatrix wrappers ----------------------------------
__device__ __forceinline__ void mma_f16(float* c, const unsigned* a, unsigned b0, unsigned b1) {
    asm volatile(
        "mma.sync.aligned.m16n8k16.row.col.f32.f16.f16.f32 "
        "{%0,%1,%2,%3}, {%4,%5,%6,%7}, {%8,%9}, {%0,%1,%2,%3};"
        : "+f"(c[0]), "+f"(c[1]), "+f"(c[2]), "+f"(c[3])
        : "r"(a[0]), "r"(a[1]), "r"(a[2]), "r"(a[3]), "r"(b0), "r"(b1));
}
__device__ __forceinline__ void ldsm_x4(unsigned* r, unsigned addr) {
    asm volatile("ldmatrix.sync.aligned.m8n8.x4.shared.b16 {%0,%1,%2,%3}, [%4];"
                 : "=r"(r[0]), "=r"(r[1]), "=r"(r[2]), "=r"(r[3]) : "r"(addr));
}
__device__ __forceinline__ void ldsm_x4t(unsigned* r, unsigned addr) {
    asm volatile("ldmatrix.sync.aligned.m8n8.x4.trans.shared.b16 {%0,%1,%2,%3}, [%4];"
                 : "=r"(r[0]), "=r"(r[1]), "=r"(r[2]), "=r"(r[3]) : "r"(addr));
}

// ---------------- degree / CSR build --------------------------------------------
__global__ void deg_init_kernel() {
    int i = blockIdx.x * blockDim.x + threadIdx.x;
    if (i < NN) g_cnt[i] = 0;
}
__global__ void deg_count_kernel(const int* __restrict__ dst) {
    int e = blockIdx.x * blockDim.x + threadIdx.x;
    if (e < EE) atomicAdd(&g_cnt[dst[e]], 1);
}
__global__ void deg_fin_kernel() {
    int i = blockIdx.x * blockDim.x + threadIdx.x;
    if (i < NN) g_deg[i] = rsqrtf((float)g_cnt[i] + 1.0f);
}
__global__ void scan1_kernel() {
    __shared__ int sc[256];
    int t = threadIdx.x;
    int i = blockIdx.x * 256 + t;
    int val = (i < NN) ? g_cnt[i] : 0;
    sc[t] = val;
    __syncthreads();
#pragma unroll
    for (int d = 1; d < 256; d <<= 1) {
        int v = (t >= d) ? sc[t - d] : 0;
        __syncthreads();
        sc[t] += v;
        __syncthreads();
    }
    if (i < NN) g_off[i] = sc[t] - val;
    if (t == 255) g_bsum[blockIdx.x] = sc[255];
}
__global__ void scan2_kernel() {
    __shared__ int sc[512];
    int t = threadIdx.x;
    int val = (t < 391) ? g_bsum[t] : 0;
    sc[t] = val;
    __syncthreads();
#pragma unroll
    for (int d = 1; d < 512; d <<= 1) {
        int v = (t >= d) ? sc[t - d] : 0;
        __syncthreads();
        sc[t] += v;
        __syncthreads();
    }
    if (t < 391) g_bsum[t] = sc[t] - val;
}
__global__ void scan3_kernel() {
    int i = blockIdx.x * blockDim.x + threadIdx.x;
    if (i < NN) {
        g_off[i] += g_bsum[i >> 8];
        g_fill[i] = 0;
    }
    if (i == 0) g_off[NN] = EE;
}
__global__ void fill_kernel(const int* __restrict__ src, const int* __restrict__ dst) {
    int e = blockIdx.x * blockDim.x + threadIdx.x;
    if (e >= EE) return;
    int d = dst[e];
    int pos = g_off[d] + atomicAdd(&g_fill[d], 1);
    g_csr[pos] = src[e];
}

// ---------------- weight / x conversions to fp16 --------------------------------
__global__ void wcvt_kernel(const float* __restrict__ W1, const float* __restrict__ W2) {
    int t = blockIdx.x * blockDim.x + threadIdx.x;
    if (t < 8192) {                         // W1: 65536 elems, 8 each
        int idx = t * 8;
        unsigned short h[8];
#pragma unroll
        for (int j = 0; j < 8; j++) {
            __half hh = __float2half_rn(W1[idx + j]);
            h[j] = *reinterpret_cast<unsigned short*>(&hh);
        }
        reinterpret_cast<uint4*>(gW1h)[t] = make_uint4(
            (unsigned)h[0] | ((unsigned)h[1] << 16), (unsigned)h[2] | ((unsigned)h[3] << 16),
            (unsigned)h[4] | ((unsigned)h[5] << 16), (unsigned)h[6] | ((unsigned)h[7] << 16));
    } else if (t < 10752) {                 // W2: 20480 elems, 8 each
        int i2 = t - 8192;
        int idx = i2 * 8;
        unsigned short h[8];
#pragma unroll
        for (int j = 0; j < 8; j++) {
            __half hh = __float2half_rn(W2[idx + j]);
            h[j] = *reinterpret_cast<unsigned short*>(&hh);
        }
        reinterpret_cast<uint4*>(gW2h)[i2] = make_uint4(
            (unsigned)h[0] | ((unsigned)h[1] << 16), (unsigned)h[2] | ((unsigned)h[3] << 16),
            (unsigned)h[4] | ((unsigned)h[5] << 16), (unsigned)h[6] | ((unsigned)h[7] << 16));
    }
}
__global__ void xcvt_kernel(const float* __restrict__ x) {
    int t = blockIdx.x * blockDim.x + threadIdx.x;     // 1.6M threads, 8 elems each
    if (t >= 1600000) return;
    float4 a = reinterpret_cast<const float4*>(x)[t * 2];
    float4 b = reinterpret_cast<const float4*>(x)[t * 2 + 1];
    __half2 p0 = __floats2half2_rn(a.x, a.y);
    __half2 p1 = __floats2half2_rn(a.z, a.w);
    __half2 p2 = __floats2half2_rn(b.x, b.y);
    __half2 p3 = __floats2half2_rn(b.z, b.w);
    reinterpret_cast<uint4*>(gX16)[t] = make_uint4(
        *reinterpret_cast<unsigned*>(&p0), *reinterpret_cast<unsigned*>(&p1),
        *reinterpret_cast<unsigned*>(&p2), *reinterpret_cast<unsigned*>(&p3));
}

// ---------------- layer-1 aggregation: fp16 CSR gather (MLP=4) + mask -----------
__global__ __launch_bounds__(256) void agg1_gather_kernel() {
    int n = blockIdx.x * 8 + (threadIdx.x >> 5);   // warp id = node (grid exact)
    int lane = threadIdx.x & 31;

    const uint2* x2 = reinterpret_cast<const uint2*>(gX16);   // 4 halfs per lane
    float dn = g_deg[n];
    float s0 = dn * dn;
    uint2 sv = x2[n * 32 + lane];
    float2 sa = __half22float2(*reinterpret_cast<__half2*>(&sv.x));
    float2 sb = __half22float2(*reinterpret_cast<__half2*>(&sv.y));
    float4 acc = make_float4(sa.x * s0, sa.y * s0, sb.x * s0, sb.y * s0);

    int beg = g_off[n], end = g_off[n + 1];
    int j = beg;
    for (; j + 4 <= end; j += 4) {
        int i0 = g_csr[j], i1 = g_csr[j + 1], i2 = g_csr[j + 2], i3 = g_csr[j + 3];
        float n0 = g_deg[i0] * dn, n1 = g_deg[i1] * dn;
        float n2 = g_deg[i2] * dn, n3 = g_deg[i3] * dn;
        uint2 v0 = x2[i0 * 32 + lane];
        uint2 v1 = x2[i1 * 32 + lane];
        uint2 v2 = x2[i2 * 32 + lane];
        uint2 v3 = x2[i3 * 32 + lane];
        float2 a0 = __half22float2(*reinterpret_cast<__half2*>(&v0.x));
        float2 b0 = __half22float2(*reinterpret_cast<__half2*>(&v0.y));
        float2 a1 = __half22float2(*reinterpret_cast<__half2*>(&v1.x));
        float2 b1 = __half22float2(*reinterpret_cast<__half2*>(&v1.y));
        float2 a2 = __half22float2(*reinterpret_cast<__half2*>(&v2.x));
        float2 b2 = __half22float2(*reinterpret_cast<__half2*>(&v2.y));
        float2 a3 = __half22float2(*reinterpret_cast<__half2*>(&v3.x));
        float2 b3 = __half22float2(*reinterpret_cast<__half2*>(&v3.y));
        acc.x += n0 * a0.x + n1 * a1.x + n2 * a2.x + n3 * a3.x;
        acc.y += n0 * a0.y + n1 * a1.y + n2 * a2.y + n3 * a3.y;
        acc.z += n0 * b0.x + n1 * b1.x + n2 * b2.x + n3 * b3.x;
        acc.w += n0 * b0.y + n1 * b1.y + n2 * b2.y + n3 * b3.y;
    }
    for (; j < end; j++) {
        int s = g_csr[j];
        float nrm = g_deg[s] * dn;
        uint2 v = x2[s * 32 + lane];
        float2 a = __half22float2(*reinterpret_cast<__half2*>(&v.x));
        float2 b = __half22float2(*reinterpret_cast<__half2*>(&v.y));
        acc.x += nrm * a.x; acc.y += nrm * a.y;
        acc.z += nrm * b.x; acc.w += nrm * b.y;
    }
    __half2 p0 = __floats2half2_rn(acc.x, acc.y);
    __half2 p1 = __floats2half2_rn(acc.z, acc.w);
    *reinterpret_cast<uint2*>(&gA16[n * 128 + lane * 4]) =
        make_uint2(*reinterpret_cast<unsigned*>(&p0), *reinterpret_cast<unsigned*>(&p1));

    // dropout mask for hidden row n (512 bits = 16 words)
    unsigned base = (unsigned)n * 512u + (unsigned)lane;
#pragma unroll
    for (int w = 0; w < 16; w++) {
        unsigned bit = tf_bit(base + (unsigned)w * 32u);
        unsigned word = __ballot_sync(0xFFFFFFFFu, bit);
        if (lane == 0) g_mask[n * 16 + w] = word;
    }
}

// ---------------- GEMM1 (mma.sync fp16): H = relu(A@W1+b1)*dropout -------------
// Writes H (fp32, required output) AND gH16 (fp16 copy for GEMM2).
#define SROW 136
__global__ __launch_bounds__(256) void gemm1_mma_kernel(const float* __restrict__ bias,
                                                        float* __restrict__ H) {
    extern __shared__ char dsm[];
    __half* sA = reinterpret_cast<__half*>(dsm);            // 34816B
    __half* sB = reinterpret_cast<__half*>(dsm + 34816);    // 34816B
    __shared__ float sBias[128];

    const int t = threadIdx.x;
    const int lane = t & 31, wid = t >> 5;
    const int m0 = blockIdx.x * 128;
    const int n0 = blockIdx.y * 128;

    if (t < 128) sBias[t] = bias[n0 + t];

#pragma unroll
    for (int i = 0; i < 8; i++) {
        int c = i * 256 + t;
        int k = c >> 4, c8 = c & 15;
        uint4 v = *reinterpret_cast<const uint4*>(&gW1h[k * 512 + n0 + c8 * 8]);
        *reinterpret_cast<uint4*>(&sB[k * SROW + c8 * 8]) = v;
    }
#pragma unroll
    for (int i = 0; i < 8; i++) {
        int c = i * 256 + t;
        int m = c >> 4, c8 = c & 15;
        int gr = m0 + m;
        uint4 v = make_uint4(0u, 0u, 0u, 0u);
        if (gr < NN) v = *reinterpret_cast<const uint4*>(&gA16[gr * 128 + c8 * 8]);
        *reinterpret_cast<uint4*>(&sA[m * SROW + c8 * 8]) = v;
    }
    __syncthreads();

    const int wm = wid & 3;
    const int wn = wid >> 2;
    float acc[2][8][4];
#pragma unroll
    for (int mf = 0; mf < 2; mf++)
#pragma unroll
        for (int nf = 0; nf < 8; nf++)
#pragma unroll
            for (int q = 0; q < 4; q++) acc[mf][nf][q] = 0.f;

    const unsigned aBase = smem_u32(sA) +
        ((unsigned)(wm * 32 + (lane & 15)) * SROW + (unsigned)((lane >> 4) * 8)) * 2u;
    const unsigned bBase = smem_u32(sB) +
        ((unsigned)(lane & 15) * SROW + (unsigned)(wn * 64 + ((lane >> 4) << 3))) * 2u;

#pragma unroll
    for (int ks = 0; ks < 8; ks++) {
        unsigned ah[2][4], bh[4][4];
#pragma unroll
        for (int mf = 0; mf < 2; mf++)
            ldsm_x4(ah[mf], aBase + (unsigned)(mf * 16 * SROW * 2) + (unsigned)(ks * 32));
#pragma unroll
        for (int j = 0; j < 4; j++)
            ldsm_x4t(bh[j], bBase + (unsigned)(ks * 16 * SROW * 2) + (unsigned)(j * 32));
#pragma unroll
        for (int mf = 0; mf < 2; mf++) {
#pragma unroll
            for (int j = 0; j < 4; j++) {
                mma_f16(acc[mf][2 * j],     ah[mf], bh[j][0], bh[j][1]);
                mma_f16(acc[mf][2 * j + 1], ah[mf], bh[j][2], bh[j][3]);
            }
        }
    }

    const int quad = lane >> 2, qt = lane & 3;
#pragma unroll
    for (int mf = 0; mf < 2; mf++) {
#pragma unroll
        for (int p = 0; p < 2; p++) {
            int row = m0 + wm * 32 + mf * 16 + quad + p * 8;
            if (row >= NN) continue;
            unsigned mw0 = g_mask[row * 16 + ((n0 + wn * 64) >> 5)];
            unsigned mw1 = g_mask[row * 16 + ((n0 + wn * 64) >> 5) + 1];
            float* hp = H + (size_t)row * 512 + n0 + wn * 64;
            __half* hp16 = gH16 + (size_t)row * 512 + n0 + wn * 64;
#pragma unroll
            for (int nf = 0; nf < 8; nf++) {
                int cl = nf * 8 + qt * 2;
                unsigned mw = (cl < 32) ? mw0 : mw1;
                int sh = cl & 31;
                float v0 = fmaxf(acc[mf][nf][p * 2 + 0] + sBias[wn * 64 + cl + 0], 0.f) * 2.f;
                float v1 = fmaxf(acc[mf][nf][p * 2 + 1] + sBias[wn * 64 + cl + 1], 0.f) * 2.f;
                float2 o;
                o.x = ((mw >> (sh + 0)) & 1u) ? v0 : 0.f;
                o.y = ((mw >> (sh + 1)) & 1u) ? v1 : 0.f;
                *reinterpret_cast<float2*>(hp + cl) = o;
                __half2 oh = __floats2half2_rn(o.x, o.y);
                *reinterpret_cast<unsigned*>(hp16 + cl) = *reinterpret_cast<unsigned*>(&oh);
            }
        }
    }
}

// ---------------- GEMM2 (mma.sync fp16): g_h2 = H16 @ W2 ------------------------
// CTA: 128 rows, N=40 (pad 48), K=512 in 8 chunks of 64. 8 warps x 16 rows.
#define AROW2 72
#define WROW2 48
__global__ __launch_bounds__(256) void gemm2_mma_kernel() {
    extern __shared__ char dsm[];
    __half* sW = reinterpret_cast<__half*>(dsm);             // 49152B [512][48]
    __half* sA = reinterpret_cast<__half*>(dsm + 49152);     // 18432B [128][72]

    const int t = threadIdx.x;
    const int lane = t & 31, wid = t >> 5;
    const int m0 = blockIdx.x * 128;

    // resident W2: 3072 uint4 slots: k = u/6, c8 = u%6 (c8==5 -> zero pad)
#pragma unroll
    for (int i = 0; i < 12; i++) {
        int u = i * 256 + t;
        int k = u / 6, c8 = u - k * 6;
        uint4 v = make_uint4(0u, 0u, 0u, 0u);
        if (c8 < 5) v = *reinterpret_cast<const uint4*>(&gW2h[k * 40 + c8 * 8]);
        *reinterpret_cast<uint4*>(&sW[k * WROW2 + c8 * 8]) = v;
    }

    float acc[5][4];
#pragma unroll
    for (int nf = 0; nf < 5; nf++)
#pragma unroll
        for (int q = 0; q < 4; q++) acc[nf][q] = 0.f;

    const unsigned aBase = smem_u32(sA) +
        ((unsigned)(wid * 16 + (lane & 15)) * AROW2 + (unsigned)((lane >> 4) * 8)) * 2u;
    const unsigned wBase = smem_u32(sW) +
        ((unsigned)(lane & 15) * WROW2 + (unsigned)((lane >> 4) * 8)) * 2u;

    for (int kc = 0; kc < 8; kc++) {
        __syncthreads();   // W ready (kc=0) / previous MMA done
        // A tile: gH16[m0..m0+127][kc*64..+63], 1024 uint4
#pragma unroll
        for (int i = 0; i < 4; i++) {
            int u = i * 256 + t;
            int m = u >> 3, c8 = u & 7;
            int gr = m0 + m;
            uint4 v = make_uint4(0u, 0u, 0u, 0u);
            if (gr < NN)
                v = *reinterpret_cast<const uint4*>(&gH16[(size_t)gr * 512 + kc * 64 + c8 * 8]);
            *reinterpret_cast<uint4*>(&sA[m * AROW2 + c8 * 8]) = v;
        }
        __syncthreads();
#pragma unroll
        for (int ks = 0; ks < 4; ks++) {
            unsigned ah[4], bw[12];
            ldsm_x4(ah, aBase + (unsigned)(ks * 32));
            unsigned ko = (unsigned)((kc * 64 + ks * 16) * WROW2 * 2);
            ldsm_x4t(&bw[0], wBase + ko);
            ldsm_x4t(&bw[4], wBase + ko + 32u);
            ldsm_x4t(&bw[8], wBase + ko + 64u);
            // frag pairs: (bw0,bw1)=n0-7 (bw2,bw3)=n8-15 (bw4,bw5)=n16-23
            //             (bw6,bw7)=n24-31 (bw8,bw9)=n32-39 ; skip n40-47 pad
            mma_f16(acc[0], ah, bw[0],  bw[1]);
            mma_f16(acc[1], ah, bw[2],  bw[3]);
            mma_f16(acc[2], ah, bw[4],  bw[5]);
            mma_f16(acc[3], ah, bw[6],  bw[7]);
            mma_f16(acc[4], ah, bw[8],  bw[9]);
        }
    }

    const int quad = lane >> 2, qt = lane & 3;
#pragma unroll
    for (int p = 0; p < 2; p++) {
        int row = m0 + wid * 16 + quad + p * 8;
        if (row >= NN) continue;
#pragma unroll
        for (int nf = 0; nf < 5; nf++) {
            int col = nf * 8 + qt * 2;
            *reinterpret_cast<float2*>(&g_h2[row * 40 + col]) =
                make_float2(acc[nf][p * 2 + 0], acc[nf][p * 2 + 1]);
        }
    }
}

// ---------------- layer-2 aggregation: CSR gather (unroll 2) --------------------
__global__ __launch_bounds__(256) void agg2_gather_kernel(const float* __restrict__ b2,
                                                          float* __restrict__ out) {
    int n = blockIdx.x * 8 + (threadIdx.x >> 5);
    int lane = threadIdx.x & 31;
    int grp = lane >= 30 ? 3 : lane / 10;
    int cl = lane - grp * 10;
    bool act = lane < 30;

    const float4* h4 = reinterpret_cast<const float4*>(g_h2);
    float dn = g_deg[n];
    float4 acc = make_float4(0.f, 0.f, 0.f, 0.f);
    if (grp == 0) {
        float4 v = h4[n * 10 + cl];
        float s0 = dn * dn;
        acc = make_float4(v.x * s0, v.y * s0, v.z * s0, v.w * s0);
    }
    int beg = g_off[n], end = g_off[n + 1];
    int j = beg + grp;
    if (act) {
        for (; j + 3 < end; j += 6) {
            int s0i = g_csr[j], s1i = g_csr[j + 3];
            float n0 = g_deg[s0i] * dn, n1 = g_deg[s1i] * dn;
            float4 v0 = h4[s0i * 10 + cl];
            float4 v1 = h4[s1i * 10 + cl];
            acc.x += n0 * v0.x + n1 * v1.x;
            acc.y += n0 * v0.y + n1 * v1.y;
            acc.z += n0 * v0.z + n1 * v1.z;
            acc.w += n0 * v0.w + n1 * v1.w;
        }
        for (; j < end; j += 3) {
            int s = g_csr[j];
            float nrm = g_deg[s] * dn;
            float4 v = h4[s * 10 + cl];
            acc.x += nrm * v.x; acc.y += nrm * v.y;
            acc.z += nrm * v.z; acc.w += nrm * v.w;
        }
    }
    const unsigned FULL = 0xFFFFFFFFu;
    acc.x += __shfl_down_sync(FULL, acc.x, 10) + __shfl_down_sync(FULL, acc.x, 20);
    acc.y += __shfl_down_sync(FULL, acc.y, 10) + __shfl_down_sync(FULL, acc.y, 20);
    acc.z += __shfl_down_sync(FULL, acc.z, 10) + __shfl_down_sync(FULL, acc.z, 20);
    acc.w += __shfl_down_sync(FULL, acc.w, 10) + __shfl_down_sync(FULL, acc.w, 20);
    if (lane < 10) {
        float4 bb = *reinterpret_cast<const float4*>(&b2[cl * 4]);
        *reinterpret_cast<float4*>(&out[n * 40 + cl * 4]) =
            make_float4(acc.x + bb.x, acc.y + bb.y, acc.z + bb.z, acc.w + bb.w);
    }
}

// ---------------- launch --------------------------------------------------------
extern "C" void kernel_launch(void* const* d_in, const int* in_sizes, int n_in,
                              void* d_out, int out_size) {
    const float* x  = (const float*)d_in[0];
    const int*   ei = (const int*)d_in[1];
    const float* W1 = (const float*)d_in[2];
    const float* b1 = (const float*)d_in[3];
    const float* W2 = (const float*)d_in[4];
    const float* b2 = (const float*)d_in[5];
    (void)in_sizes; (void)n_in; (void)out_size;

    float* out = (float*)d_out;           // [NN, 40]
    float* hidden = out + NN * 40;        // [NN, 512]
    const int* src = ei;
    const int* dst = ei + EE;

    const int GEMM1_SMEM = 69632;
    cudaFuncSetAttribute(gemm1_mma_kernel,
                         cudaFuncAttributeMaxDynamicSharedMemorySize, GEMM1_SMEM);
    const int GEMM2_SMEM = 67584;
    cudaFuncSetAttribute(gemm2_mma_kernel,
                         cudaFuncAttributeMaxDynamicSharedMemorySize, GEMM2_SMEM);

    // degree + CSR build (+ weight/x conversions interleaved)
    deg_init_kernel<<<(NN + 255) / 256, 256>>>();
    deg_count_kernel<<<(EE + 255) / 256, 256>>>(dst);
    wcvt_kernel<<<42, 256>>>(W1, W2);
    xcvt_kernel<<<6250, 256>>>(x);
    deg_fin_kernel<<<(NN + 255) / 256, 256>>>();
    scan1_kernel<<<391, 256>>>();
    scan2_kernel<<<1, 512>>>();
    scan3_kernel<<<(NN + 255) / 256, 256>>>();
    fill_kernel<<<(EE + 255) / 256, 256>>>(src, dst);

    // layer-1 aggregation (fp16 gather, MLP=4) + fused dropout mask
    agg1_gather_kernel<<<12500, 256>>>();

    gemm1_mma_kernel<<<dim3((NN + 127) / 128, 4), 256, GEMM1_SMEM>>>(b1, hidden);
    gemm2_mma_kernel<<<(NN + 127) / 128, 256, GEMM2_SMEM>>>();

    // layer-2 aggregation (gather, unroll 2) + fused b2
    agg2_gather_kernel<<<12500, 256>>>(b2, out);
}

// round 12
// speedup vs baseline: 1.9536x; 1.0500x over previous
#include <cuda_runtime.h>
#include <cuda_fp16.h>
#include <cstdint>

#define NN 100000
#define EE 800000

// ---------------- scratch (__device__ globals; no allocation allowed) ----------
__device__ float g_deg[NN];                       // dinv_sqrt
__device__ int   g_cnt[NN];                       // in-degree counts
__device__ int   g_off[NN + 1];                   // CSR offsets (by dst)
__device__ int   g_fill[NN];                      // fill cursors
__device__ int   g_csr[EE];                       // src ids grouped by dst
__device__ int   g_bsum[512];                     // scan block sums
__device__ __align__(16) __half gX16[NN * 128];   // x in fp16 (agg1 gather source)
__device__ __align__(16) __half gA16[NN * 128];   // aggregated X, fp16 (GEMM1 A)
__device__ __align__(16) __half gH16[NN * 512];   // hidden in fp16 (GEMM2 A)
__device__ __align__(16) float g_h2[NN * 40];     // hidden @ W2 (pre-aggregation)
__device__ unsigned g_mask[800000];               // keep-bits for cols 0-255 only
__device__ __align__(16) __half gW1h[128 * 512];  // W1 fp16, k-major
__device__ __align__(16) __half gW2h[512 * 40];   // W2 fp16, k-major

// ---------------- small helpers ------------------------------------------------
__device__ __forceinline__ unsigned smem_u32(const void* p) {
    unsigned a;
    asm("{ .reg .u64 t; cvta.to.shared.u64 t, %1; cvt.u32.u64 %0, t; }" : "=r"(a) : "l"(p));
    return a;
}

// JAX threefry2x32 with key = (0, 42)
__device__ __forceinline__ void threefry42(unsigned& x0, unsigned& x1) {
    const unsigned ks0 = 0u, ks1 = 42u, ks2 = 0x1BD11BDAu ^ 42u;
    x0 += ks0; x1 += ks1;
#define TFR(r) { x0 += x1; x1 = (x1 << (r)) | (x1 >> (32 - (r))); x1 ^= x0; }
    TFR(13) TFR(15) TFR(26) TFR(6)   x0 += ks1; x1 += ks2 + 1u;
    TFR(17) TFR(29) TFR(16) TFR(24)  x0 += ks2; x1 += ks0 + 2u;
    TFR(13) TFR(15) TFR(26) TFR(6)   x0 += ks0; x1 += ks1 + 3u;
    TFR(17) TFR(29) TFR(16) TFR(24)  x0 += ks1; x1 += ks2 + 4u;
    TFR(13) TFR(15) TFR(26) TFR(6)   x0 += ks2; x1 += ks0 + 5u;
#undef TFR
}
__device__ __forceinline__ unsigned tf_bit(unsigned idx) {
    unsigned x0 = 0u, x1 = idx;
    threefry42(x0, x1);
    return (~(x0 ^ x1)) >> 31;
}

// ---------------- mma.sync / ldmatrix wrappers ----------------------------------
__device__ __forceinline__ void mma_f16(float* c, const unsigned* a, unsigned b0, unsigned b1) {
    asm volatile(
        "mma.sync.aligned.m16n8k16.row.col.f32.f16.f16.f32 "
        "{%0,%1,%2,%3}, {%4,%5,%6,%7}, {%8,%9}, {%0,%1,%2,%3};"
        : "+f"(c[0]), "+f"(c[1]), "+f"(c[2]), "+f"(c[3])
        : "r"(a[0]), "r"(a[1]), "r"(a[2]), "r"(a[3]), "r"(b0), "r"(b1));
}
__device__ __forceinline__ void ldsm_x4(unsigned* r, unsigned addr) {
    asm volatile("ldmatrix.sync.aligned.m8n8.x4.shared.b16 {%0,%1,%2,%3}, [%4];"
                 : "=r"(r[0]), "=r"(r[1]), "=r"(r[2]), "=r"(r[3]) : "r"(addr));
}
__device__ __forceinline__ void ldsm_x4t(unsigned* r, unsigned addr) {
    asm volatile("ldmatrix.sync.aligned.m8n8.x4.trans.shared.b16 {%0,%1,%2,%3}, [%4];"
                 : "=r"(r[0]), "=r"(r[1]), "=r"(r[2]), "=r"(r[3]) : "r"(addr));
}

// ---------------- degree / CSR build --------------------------------------------
__global__ void deg_init_kernel() {
    int i = blockIdx.x * blockDim.x + threadIdx.x;
    if (i < NN) g_cnt[i] = 0;
}
__global__ void deg_count_kernel(const int* __restrict__ dst) {
    int e = blockIdx.x * blockDim.x + threadIdx.x;
    if (e < EE) atomicAdd(&g_cnt[dst[e]], 1);
}
// scan1 + deg finalize fused
__global__ void scan1_kernel() {
    __shared__ int sc[256];
    int t = threadIdx.x;
    int i = blockIdx.x * 256 + t;
    int val = (i < NN) ? g_cnt[i] : 0;
    if (i < NN) g_deg[i] = rsqrtf((float)val + 1.0f);
    sc[t] = val;
    __syncthreads();
#pragma unroll
    for (int d = 1; d < 256; d <<= 1) {
        int v = (t >= d) ? sc[t - d] : 0;
        __syncthreads();
        sc[t] += v;
        __syncthreads();
    }
    if (i < NN) g_off[i] = sc[t] - val;
    if (t == 255) g_bsum[blockIdx.x] = sc[255];
}
__global__ void scan2_kernel() {
    __shared__ int sc[512];
    int t = threadIdx.x;
    int val = (t < 391) ? g_bsum[t] : 0;
    sc[t] = val;
    __syncthreads();
#pragma unroll
    for (int d = 1; d < 512; d <<= 1) {
        int v = (t >= d) ? sc[t - d] : 0;
        __syncthreads();
        sc[t] += v;
        __syncthreads();
    }
    if (t < 391) g_bsum[t] = sc[t] - val;
}
__global__ void scan3_kernel() {
    int i = blockIdx.x * blockDim.x + threadIdx.x;
    if (i < NN) {
        g_off[i] += g_bsum[i >> 8];
        g_fill[i] = 0;
    }
    if (i == 0) g_off[NN] = EE;
}
__global__ void fill_kernel(const int* __restrict__ src, const int* __restrict__ dst) {
    int e = blockIdx.x * blockDim.x + threadIdx.x;
    if (e >= EE) return;
    int d = dst[e];
    int pos = g_off[d] + atomicAdd(&g_fill[d], 1);
    g_csr[pos] = src[e];
}

// ---------------- combined fp16 conversions: W1, W2, x --------------------------
// blocks 0..41: weights (10752 slots); blocks 42..6291: x (1.6M slots)
__global__ void cvt_kernel(const float* __restrict__ W1, const float* __restrict__ W2,
                           const float* __restrict__ x) {
    int b = blockIdx.x;
    if (b < 42) {
        int t = b * 256 + threadIdx.x;
        if (t < 8192) {                     // W1: 65536 elems, 8 each
            int idx = t * 8;
            unsigned short h[8];
#pragma unroll
            for (int j = 0; j < 8; j++) {
                __half hh = __float2half_rn(W1[idx + j]);
                h[j] = *reinterpret_cast<unsigned short*>(&hh);
            }
            reinterpret_cast<uint4*>(gW1h)[t] = make_uint4(
                (unsigned)h[0] | ((unsigned)h[1] << 16), (unsigned)h[2] | ((unsigned)h[3] << 16),
                (unsigned)h[4] | ((unsigned)h[5] << 16), (unsigned)h[6] | ((unsigned)h[7] << 16));
        } else if (t < 10752) {             // W2: 20480 elems, 8 each
            int i2 = t - 8192;
            int idx = i2 * 8;
            unsigned short h[8];
#pragma unroll
            for (int j = 0; j < 8; j++) {
                __half hh = __float2half_rn(W2[idx + j]);
                h[j] = *reinterpret_cast<unsigned short*>(&hh);
            }
            reinterpret_cast<uint4*>(gW2h)[i2] = make_uint4(
                (unsigned)h[0] | ((unsigned)h[1] << 16), (unsigned)h[2] | ((unsigned)h[3] << 16),
                (unsigned)h[4] | ((unsigned)h[5] << 16), (unsigned)h[6] | ((unsigned)h[7] << 16));
        }
    } else {
        int t = (b - 42) * 256 + threadIdx.x;           // 1.6M slots, 8 elems each
        if (t >= 1600000) return;
        float4 a = reinterpret_cast<const float4*>(x)[t * 2];
        float4 c = reinterpret_cast<const float4*>(x)[t * 2 + 1];
        __half2 p0 = __floats2half2_rn(a.x, a.y);
        __half2 p1 = __floats2half2_rn(a.z, a.w);
        __half2 p2 = __floats2half2_rn(c.x, c.y);
        __half2 p3 = __floats2half2_rn(c.z, c.w);
        reinterpret_cast<uint4*>(gX16)[t] = make_uint4(
            *reinterpret_cast<unsigned*>(&p0), *reinterpret_cast<unsigned*>(&p1),
            *reinterpret_cast<unsigned*>(&p2), *reinterpret_cast<unsigned*>(&p3));
    }
}

// ---------------- layer-1 aggregation: fp16 CSR gather (MLP=4) + half mask ------
__global__ __launch_bounds__(256) void agg1_gather_kernel() {
    int n = blockIdx.x * 8 + (threadIdx.x >> 5);   // warp id = node (grid exact)
    int lane = threadIdx.x & 31;

    const uint2* x2 = reinterpret_cast<const uint2*>(gX16);   // 4 halfs per lane
    float dn = g_deg[n];
    float s0 = dn * dn;
    uint2 sv = x2[n * 32 + lane];
    float2 sa = __half22float2(*reinterpret_cast<__half2*>(&sv.x));
    float2 sb = __half22float2(*reinterpret_cast<__half2*>(&sv.y));
    float4 acc = make_float4(sa.x * s0, sa.y * s0, sb.x * s0, sb.y * s0);

    int beg = g_off[n], end = g_off[n + 1];
    int j = beg;
    for (; j + 4 <= end; j += 4) {
        int i0 = g_csr[j], i1 = g_csr[j + 1], i2 = g_csr[j + 2], i3 = g_csr[j + 3];
        float n0 = g_deg[i0] * dn, n1 = g_deg[i1] * dn;
        float n2 = g_deg[i2] * dn, n3 = g_deg[i3] * dn;
        uint2 v0 = x2[i0 * 32 + lane];
        uint2 v1 = x2[i1 * 32 + lane];
        uint2 v2 = x2[i2 * 32 + lane];
        uint2 v3 = x2[i3 * 32 + lane];
        float2 a0 = __half22float2(*reinterpret_cast<__half2*>(&v0.x));
        float2 b0 = __half22float2(*reinterpret_cast<__half2*>(&v0.y));
        float2 a1 = __half22float2(*reinterpret_cast<__half2*>(&v1.x));
        float2 b1 = __half22float2(*reinterpret_cast<__half2*>(&v1.y));
        float2 a2 = __half22float2(*reinterpret_cast<__half2*>(&v2.x));
        float2 b2 = __half22float2(*reinterpret_cast<__half2*>(&v2.y));
        float2 a3 = __half22float2(*reinterpret_cast<__half2*>(&v3.x));
        float2 b3 = __half22float2(*reinterpret_cast<__half2*>(&v3.y));
        acc.x += n0 * a0.x + n1 * a1.x + n2 * a2.x + n3 * a3.x;
        acc.y += n0 * a0.y + n1 * a1.y + n2 * a2.y + n3 * a3.y;
        acc.z += n0 * b0.x + n1 * b1.x + n2 * b2.x + n3 * b3.x;
        acc.w += n0 * b0.y + n1 * b1.y + n2 * b2.y + n3 * b3.y;
    }
    for (; j < end; j++) {
        int s = g_csr[j];
        float nrm = g_deg[s] * dn;
        uint2 v = x2[s * 32 + lane];
        float2 a = __half22float2(*reinterpret_cast<__half2*>(&v.x));
        float2 b = __half22float2(*reinterpret_cast<__half2*>(&v.y));
        acc.x += nrm * a.x; acc.y += nrm * a.y;
        acc.z += nrm * b.x; acc.w += nrm * b.y;
    }
    __half2 p0 = __floats2half2_rn(acc.x, acc.y);
    __half2 p1 = __floats2half2_rn(acc.z, acc.w);
    *reinterpret_cast<uint2*>(&gA16[n * 128 + lane * 4]) =
        make_uint2(*reinterpret_cast<unsigned*>(&p0), *reinterpret_cast<unsigned*>(&p1));

    // dropout mask for hidden row n, cols 0-255 only (8 words); cols 256-511
    // are computed inline in gemm1's epilogue (split across both kernels'
    // memory/tensor shadows).
    unsigned base = (unsigned)n * 512u + (unsigned)lane;
#pragma unroll
    for (int w = 0; w < 8; w++) {
        unsigned bit = tf_bit(base + (unsigned)w * 32u);
        unsigned word = __ballot_sync(0xFFFFFFFFu, bit);
        if (lane == 0) g_mask[n * 8 + w] = word;
    }
}

// ---------------- GEMM1 (mma.sync fp16): H = relu(A@W1+b1)*dropout -------------
// Writes H (fp32) AND gH16 (fp16 for GEMM2). Mask: cols<256 read from g_mask;
// cols>=256 threefry evals inline in the epilogue (alu pipe is idle here).
#define SROW 136
__global__ __launch_bounds__(256) void gemm1_mma_kernel(const float* __restrict__ bias,
                                                        float* __restrict__ H) {
    extern __shared__ char dsm[];
    __half* sA = reinterpret_cast<__half*>(dsm);            // 34816B
    __half* sB = reinterpret_cast<__half*>(dsm + 34816);    // 34816B
    __shared__ float sBias[128];

    const int t = threadIdx.x;
    const int lane = t & 31, wid = t >> 5;
    const int m0 = blockIdx.x * 128;
    const int n0 = blockIdx.y * 128;

    if (t < 128) sBias[t] = bias[n0 + t];

#pragma unroll
    for (int i = 0; i < 8; i++) {
        int c = i * 256 + t;
        int k = c >> 4, c8 = c & 15;
        uint4 v = *reinterpret_cast<const uint4*>(&gW1h[k * 512 + n0 + c8 * 8]);
        *reinterpret_cast<uint4*>(&sB[k * SROW + c8 * 8]) = v;
    }
#pragma unroll
    for (int i = 0; i < 8; i++) {
        int c = i * 256 + t;
        int m = c >> 4, c8 = c & 15;
        int gr = m0 + m;
        uint4 v = make_uint4(0u, 0u, 0u, 0u);
        if (gr < NN) v = *reinterpret_cast<const uint4*>(&gA16[gr * 128 + c8 * 8]);
        *reinterpret_cast<uint4*>(&sA[m * SROW + c8 * 8]) = v;
    }
    __syncthreads();

    const int wm = wid & 3;
    const int wn = wid >> 2;
    float acc[2][8][4];
#pragma unroll
    for (int mf = 0; mf < 2; mf++)
#pragma unroll
        for (int nf = 0; nf < 8; nf++)
#pragma unroll
            for (int q = 0; q < 4; q++) acc[mf][nf][q] = 0.f;

    const unsigned aBase = smem_u32(sA) +
        ((unsigned)(wm * 32 + (lane & 15)) * SROW + (unsigned)((lane >> 4) * 8)) * 2u;
    const unsigned bBase = smem_u32(sB) +
        ((unsigned)(lane & 15) * SROW + (unsigned)(wn * 64 + ((lane >> 4) << 3))) * 2u;

#pragma unroll
    for (int ks = 0; ks < 8; ks++) {
        unsigned ah[2][4], bh[4][4];
#pragma unroll
        for (int mf = 0; mf < 2; mf++)
            ldsm_x4(ah[mf], aBase + (unsigned)(mf * 16 * SROW * 2) + (unsigned)(ks * 32));
#pragma unroll
        for (int j = 0; j < 4; j++)
            ldsm_x4t(bh[j], bBase + (unsigned)(ks * 16 * SROW * 2) + (unsigned)(j * 32));
#pragma unroll
        for (int mf = 0; mf < 2; mf++) {
#pragma unroll
            for (int j = 0; j < 4; j++) {
                mma_f16(acc[mf][2 * j],     ah[mf], bh[j][0], bh[j][1]);
                mma_f16(acc[mf][2 * j + 1], ah[mf], bh[j][2], bh[j][3]);
            }
        }
    }

    const int quad = lane >> 2, qt = lane & 3;
    const bool lowCols = (n0 < 256);
#pragma unroll
    for (int mf = 0; mf < 2; mf++) {
#pragma unroll
        for (int p = 0; p < 2; p++) {
            int row = m0 + wm * 32 + mf * 16 + quad + p * 8;
            if (row >= NN) continue;
            const unsigned colbase = (unsigned)(n0 + wn * 64);
            unsigned mw0 = 0u, mw1 = 0u;
            if (lowCols) {
                mw0 = g_mask[row * 8 + (colbase >> 5)];
                mw1 = g_mask[row * 8 + (colbase >> 5) + 1];
            }
            const unsigned rowbase = (unsigned)row * 512u + colbase;
            float* hp = H + (size_t)row * 512 + n0 + wn * 64;
            __half* hp16 = gH16 + (size_t)row * 512 + n0 + wn * 64;
#pragma unroll
            for (int nf = 0; nf < 8; nf++) {
                int cl = nf * 8 + qt * 2;
                unsigned keep0, keep1;
                if (lowCols) {
                    unsigned mw = (cl < 32) ? mw0 : mw1;
                    int sh = cl & 31;
                    keep0 = (mw >> (sh + 0)) & 1u;
                    keep1 = (mw >> (sh + 1)) & 1u;
                } else {
                    keep0 = tf_bit(rowbase + (unsigned)cl);
                    keep1 = tf_bit(rowbase + (unsigned)cl + 1u);
                }
                float v0 = fmaxf(acc[mf][nf][p * 2 + 0] + sBias[wn * 64 + cl + 0], 0.f) * 2.f;
                float v1 = fmaxf(acc[mf][nf][p * 2 + 1] + sBias[wn * 64 + cl + 1], 0.f) * 2.f;
                float2 o;
                o.x = keep0 ? v0 : 0.f;
                o.y = keep1 ? v1 : 0.f;
                *reinterpret_cast<float2*>(hp + cl) = o;
                __half2 oh = __floats2half2_rn(o.x, o.y);
                *reinterpret_cast<unsigned*>(hp16 + cl) = *reinterpret_cast<unsigned*>(&oh);
            }
        }
    }
}

// ---------------- GEMM2 (mma.sync fp16): g_h2 = H16 @ W2 ------------------------
#define AROW2 72
#define WROW2 48
__global__ __launch_bounds__(256) void gemm2_mma_kernel() {
    extern __shared__ char dsm[];
    __half* sW = reinterpret_cast<__half*>(dsm);             // 49152B [512][48]
    __half* sA = reinterpret_cast<__half*>(dsm + 49152);     // 18432B [128][72]

    const int t = threadIdx.x;
    const int lane = t & 31, wid = t >> 5;
    const int m0 = blockIdx.x * 128;

#pragma unroll
    for (int i = 0; i < 12; i++) {
        int u = i * 256 + t;
        int k = u / 6, c8 = u - k * 6;
        uint4 v = make_uint4(0u, 0u, 0u, 0u);
        if (c8 < 5) v = *reinterpret_cast<const uint4*>(&gW2h[k * 40 + c8 * 8]);
        *reinterpret_cast<uint4*>(&sW[k * WROW2 + c8 * 8]) = v;
    }

    float acc[5][4];
#pragma unroll
    for (int nf = 0; nf < 5; nf++)
#pragma unroll
        for (int q = 0; q < 4; q++) acc[nf][q] = 0.f;

    const unsigned aBase = smem_u32(sA) +
        ((unsigned)(wid * 16 + (lane & 15)) * AROW2 + (unsigned)((lane >> 4) * 8)) * 2u;
    const unsigned wBase = smem_u32(sW) +
        ((unsigned)(lane & 15) * WROW2 + (unsigned)((lane >> 4) * 8)) * 2u;

    for (int kc = 0; kc < 8; kc++) {
        __syncthreads();
#pragma unroll
        for (int i = 0; i < 4; i++) {
            int u = i * 256 + t;
            int m = u >> 3, c8 = u & 7;
            int gr = m0 + m;
            uint4 v = make_uint4(0u, 0u, 0u, 0u);
            if (gr < NN)
                v = *reinterpret_cast<const uint4*>(&gH16[(size_t)gr * 512 + kc * 64 + c8 * 8]);
            *reinterpret_cast<uint4*>(&sA[m * AROW2 + c8 * 8]) = v;
        }
        __syncthreads();
#pragma unroll
        for (int ks = 0; ks < 4; ks++) {
            unsigned ah[4], bw[12];
            ldsm_x4(ah, aBase + (unsigned)(ks * 32));
            unsigned ko = (unsigned)((kc * 64 + ks * 16) * WROW2 * 2);
            ldsm_x4t(&bw[0], wBase + ko);
            ldsm_x4t(&bw[4], wBase + ko + 32u);
            ldsm_x4t(&bw[8], wBase + ko + 64u);
            mma_f16(acc[0], ah, bw[0],  bw[1]);
            mma_f16(acc[1], ah, bw[2],  bw[3]);
            mma_f16(acc[2], ah, bw[4],  bw[5]);
            mma_f16(acc[3], ah, bw[6],  bw[7]);
            mma_f16(acc[4], ah, bw[8],  bw[9]);
        }
    }

    const int quad = lane >> 2, qt = lane & 3;
#pragma unroll
    for (int p = 0; p < 2; p++) {
        int row = m0 + wid * 16 + quad + p * 8;
        if (row >= NN) continue;
#pragma unroll
        for (int nf = 0; nf < 5; nf++) {
            int col = nf * 8 + qt * 2;
            *reinterpret_cast<float2*>(&g_h2[row * 40 + col]) =
                make_float2(acc[nf][p * 2 + 0], acc[nf][p * 2 + 1]);
        }
    }
}

// ---------------- layer-2 aggregation: CSR gather (unroll 2) --------------------
__global__ __launch_bounds__(256) void agg2_gather_kernel(const float* __restrict__ b2,
                                                          float* __restrict__ out) {
    int n = blockIdx.x * 8 + (threadIdx.x >> 5);
    int lane = threadIdx.x & 31;
    int grp = lane >= 30 ? 3 : lane / 10;
    int cl = lane - grp * 10;
    bool act = lane < 30;

    const float4* h4 = reinterpret_cast<const float4*>(g_h2);
    float dn = g_deg[n];
    float4 acc = make_float4(0.f, 0.f, 0.f, 0.f);
    if (grp == 0) {
        float4 v = h4[n * 10 + cl];
        float s0 = dn * dn;
        acc = make_float4(v.x * s0, v.y * s0, v.z * s0, v.w * s0);
    }
    int beg = g_off[n], end = g_off[n + 1];
    int j = beg + grp;
    if (act) {
        for (; j + 3 < end; j += 6) {
            int s0i = g_csr[j], s1i = g_csr[j + 3];
            float n0 = g_deg[s0i] * dn, n1 = g_deg[s1i] * dn;
            float4 v0 = h4[s0i * 10 + cl];
            float4 v1 = h4[s1i * 10 + cl];
            acc.x += n0 * v0.x + n1 * v1.x;
            acc.y += n0 * v0.y + n1 * v1.y;
            acc.z += n0 * v0.z + n1 * v1.z;
            acc.w += n0 * v0.w + n1 * v1.w;
        }
        for (; j < end; j += 3) {
            int s = g_csr[j];
            float nrm = g_deg[s] * dn;
            float4 v = h4[s * 10 + cl];
            acc.x += nrm * v.x; acc.y += nrm * v.y;
            acc.z += nrm * v.z; acc.w += nrm * v.w;
        }
    }
    const unsigned FULL = 0xFFFFFFFFu;
    acc.x += __shfl_down_sync(FULL, acc.x, 10) + __shfl_down_sync(FULL, acc.x, 20);
    acc.y += __shfl_down_sync(FULL, acc.y, 10) + __shfl_down_sync(FULL, acc.y, 20);
    acc.z += __shfl_down_sync(FULL, acc.z, 10) + __shfl_down_sync(FULL, acc.z, 20);
    acc.w += __shfl_down_sync(FULL, acc.w, 10) + __shfl_down_sync(FULL, acc.w, 20);
    if (lane < 10) {
        float4 bb = *reinterpret_cast<const float4*>(&b2[cl * 4]);
        *reinterpret_cast<float4*>(&out[n * 40 + cl * 4]) =
            make_float4(acc.x + bb.x, acc.y + bb.y, acc.z + bb.z, acc.w + bb.w);
    }
}

// ---------------- launch --------------------------------------------------------
extern "C" void kernel_launch(void* const* d_in, const int* in_sizes, int n_in,
                              void* d_out, int out_size) {
    const float* x  = (const float*)d_in[0];
    const int*   ei = (const int*)d_in[1];
    const float* W1 = (const float*)d_in[2];
    const float* b1 = (const float*)d_in[3];
    const float* W2 = (const float*)d_in[4];
    const float* b2 = (const float*)d_in[5];
    (void)in_sizes; (void)n_in; (void)out_size;

    float* out = (float*)d_out;           // [NN, 40]
    float* hidden = out + NN * 40;        // [NN, 512]
    const int* src = ei;
    const int* dst = ei + EE;

    const int GEMM1_SMEM = 69632;
    cudaFuncSetAttribute(gemm1_mma_kernel,
                         cudaFuncAttributeMaxDynamicSharedMemorySize, GEMM1_SMEM);
    const int GEMM2_SMEM = 67584;
    cudaFuncSetAttribute(gemm2_mma_kernel,
                         cudaFuncAttributeMaxDynamicSharedMemorySize, GEMM2_SMEM);

    // degree + CSR build + fp16 conversions
    deg_init_kernel<<<(NN + 255) / 256, 256>>>();
    deg_count_kernel<<<(EE + 255) / 256, 256>>>(dst);
    cvt_kernel<<<6292, 256>>>(W1, W2, x);
    scan1_kernel<<<391, 256>>>();         // also finalizes g_deg
    scan2_kernel<<<1, 512>>>();
    scan3_kernel<<<(NN + 255) / 256, 256>>>();
    fill_kernel<<<(EE + 255) / 256, 256>>>(src, dst);

    // layer-1 aggregation (fp16 gather, MLP=4) + mask cols 0-255
    agg1_gather_kernel<<<12500, 256>>>();

    gemm1_mma_kernel<<<dim3((NN + 127) / 128, 4), 256, GEMM1_SMEM>>>(b1, hidden);
    gemm2_mma_kernel<<<(NN + 127) / 128, 256, GEMM2_SMEM>>>();

    // layer-2 aggregation (gather, unroll 2) + fused b2
    agg2_gather_kernel<<<12500, 256>>>(b2, out);
}